// round 9
// baseline (speedup 1.0000x reference)
#include <cuda_runtime.h>
#include <cuda_bf16.h>
#include <cstdint>
#include <math.h>

#define BATCH   2
#define NSEQ    2048
#define DMODEL  512
#define NHEADS  8
#define DH      64
#define KP      32
#define KEXP    1536
#define TAU_F   6.283185307179586f

// ---------------- scratch (static device memory; no allocations) ----------------
__device__ __nv_bfloat16 g_qe[(size_t)BATCH * NHEADS * NSEQ * 128];  // [qh|ql]
__device__ __nv_bfloat16 g_ke[(size_t)BATCH * NHEADS * NSEQ * 128];  // [kh|kl]
__device__ __nv_bfloat16 g_vh[(size_t)BATCH * NHEADS * NSEQ * DH];
__device__ __nv_bfloat16 g_vl[(size_t)BATCH * NHEADS * NSEQ * DH];
__device__ float g_cos[NHEADS * NSEQ * KP];
__device__ float g_sin[NHEADS * NSEQ * KP];
__device__ float g_bias[NHEADS * NSEQ];                             // lam*S_n/KP per head
__device__ float g_att[(size_t)BATCH * NSEQ * DMODEL];              // (b,n,h*dh)
__device__ __nv_bfloat16 g_aexp[(size_t)BATCH * NSEQ * KEXP];       // A' 4096x1536
__device__ __nv_bfloat16 g_bexp[(size_t)3 * DMODEL * KEXP];         // B' 1536x1536
__device__ __nv_bfloat16 g_bexp2[(size_t)DMODEL * KEXP];            // B2' 512x1536

__constant__ float c_zim[KP] = {
    14.134725142f, 21.022039639f, 25.01085758f,  30.424876126f,
    32.935061588f, 37.586178159f, 40.918719012f, 43.327073281f,
    48.005150881f, 49.773832478f, 52.970321478f, 56.446247697f,
    59.347044003f, 60.831778525f, 65.112544048f, 67.079810529f,
    69.546401711f, 72.067157674f, 75.704690699f, 77.144840069f,
    79.33737502f,  82.910380854f, 84.735492981f, 87.425274613f,
    88.809111208f, 92.491899271f, 94.651344041f, 95.870634228f,
    98.831194218f, 101.317851006f, 103.72553804f, 105.446623052f};

// ---------------- warp-MMA / async helpers (portable sm_80+ path) ----------------
__device__ __forceinline__ uint32_t smem_u32(const void* p) {
    uint32_t a;
    asm("{ .reg .u64 t; cvta.to.shared.u64 t, %1; cvt.u32.u64 %0, t; }" : "=r"(a) : "l"(p));
    return a;
}
__device__ __forceinline__ void ldsm4(uint32_t* r, uint32_t a) {
    asm volatile("ldmatrix.sync.aligned.m8n8.x4.shared.b16 {%0,%1,%2,%3}, [%4];"
                 : "=r"(r[0]), "=r"(r[1]), "=r"(r[2]), "=r"(r[3]) : "r"(a));
}
__device__ __forceinline__ void ldsm4t(uint32_t* r, uint32_t a) {
    asm volatile("ldmatrix.sync.aligned.m8n8.x4.trans.shared.b16 {%0,%1,%2,%3}, [%4];"
                 : "=r"(r[0]), "=r"(r[1]), "=r"(r[2]), "=r"(r[3]) : "r"(a));
}
__device__ __forceinline__ void mma16816(float* c, const uint32_t* a, uint32_t b0, uint32_t b1) {
    asm volatile("mma.sync.aligned.m16n8k16.row.col.f32.bf16.bf16.f32 "
                 "{%0,%1,%2,%3}, {%4,%5,%6,%7}, {%8,%9}, {%0,%1,%2,%3};"
                 : "+f"(c[0]), "+f"(c[1]), "+f"(c[2]), "+f"(c[3])
                 : "r"(a[0]), "r"(a[1]), "r"(a[2]), "r"(a[3]), "r"(b0), "r"(b1));
}
__device__ __forceinline__ void cpasync16(uint32_t dst, const void* src) {
    asm volatile("cp.async.cg.shared.global [%0], [%1], 16;" :: "r"(dst), "l"(src));
}
__device__ __forceinline__ void cpcommit() {
    asm volatile("cp.async.commit_group;");
}
template <int N>
__device__ __forceinline__ void cpwait() {
    asm volatile("cp.async.wait_group %0;" :: "n"(N));
}

// ---------------- bf16 mma GEMM, 4 warps x (64x64) warp tile, 4-stage cp.async ----
// C[M,Ntot] = A'[M,1536] @ B'[Ntot,1536]^T, 128x128 CTA tile, K-tiles of 32.
#define KT (KEXP / 32)
#define SWZ(r, bc) ((uint32_t)((r) * 64 + ((bc) ^ ((((r) >> 1) & 3) << 4))))
#define GSTAGES 4
#define GSTG_SZ 16384               // A(8KB) + B(8KB) per stage
#define GEMM_SMEM (GSTAGES * GSTG_SZ)

template <int EPI>
__global__ __launch_bounds__(128, 2) void mmagemm(const __nv_bfloat16* __restrict__ A,
                                                  const __nv_bfloat16* __restrict__ Bm,
                                                  float* __restrict__ C, int Ntot) {
    extern __shared__ char gsm[];
    const uint32_t sbase = smem_u32(gsm);

    const int tid = threadIdx.x;
    const int lane = tid & 31;
    const int wid = tid >> 5;
    const int wm = (wid & 1) * 64;
    const int wn = (wid >> 1) * 64;
    const int row0 = blockIdx.y * 128;
    const int col0 = blockIdx.x * 128;

    // ldmatrix per-lane offsets
    const int lr = (lane & 7) + ((lane >> 3) & 1) * 8;
    const int kh = (lane >> 4) * 16;
    uint32_t aoff[4][2], boff[4][2];
#pragma unroll
    for (int mi = 0; mi < 4; mi++)
#pragma unroll
        for (int ks = 0; ks < 2; ks++) aoff[mi][ks] = SWZ(wm + mi * 16 + lr, ks * 32 + kh);
#pragma unroll
    for (int ng = 0; ng < 4; ng++)
#pragma unroll
        for (int ks = 0; ks < 2; ks++) boff[ng][ks] = SWZ(wn + ng * 16 + lr, ks * 32 + kh);

    // cp.async mapping: 128 threads, each covers 4 rows (r_ld+32p) x 16B for A and B
    const int r_ld = tid >> 2, cu_ld = tid & 3;
    uint32_t so[4];
#pragma unroll
    for (int p = 0; p < 4; p++) so[p] = SWZ(r_ld + 32 * p, cu_ld * 16);
    const __nv_bfloat16* ap = &A[(size_t)(row0 + r_ld) * KEXP + cu_ld * 8];
    const __nv_bfloat16* bp = &Bm[(size_t)(col0 + r_ld) * KEXP + cu_ld * 8];

    auto load_tile = [&](int t) {
        const uint32_t st = sbase + (uint32_t)((t % GSTAGES) * GSTG_SZ);
        const int k0 = t * 32;
#pragma unroll
        for (int p = 0; p < 4; p++) {
            cpasync16(st + so[p], ap + (size_t)32 * p * KEXP + k0);
            cpasync16(st + 8192 + so[p], bp + (size_t)32 * p * KEXP + k0);
        }
        cpcommit();
    };
    load_tile(0);
    load_tile(1);
    load_tile(2);

    float acc[4][8][4];
#pragma unroll
    for (int mi = 0; mi < 4; mi++)
#pragma unroll
        for (int nf = 0; nf < 8; nf++)
#pragma unroll
            for (int q = 0; q < 4; q++) acc[mi][nf][q] = 0.0f;

    for (int t = 0; t < KT; t++) {
        cpwait<2>();
        __syncthreads();
        const uint32_t baseA = sbase + (uint32_t)((t % GSTAGES) * GSTG_SZ);
        const uint32_t baseB = baseA + 8192;
#pragma unroll
        for (int ks = 0; ks < 2; ks++) {
            uint32_t af[4][4], bfr[4][4];
#pragma unroll
            for (int mi = 0; mi < 4; mi++) ldsm4(af[mi], baseA + aoff[mi][ks]);
#pragma unroll
            for (int ng = 0; ng < 4; ng++) ldsm4(bfr[ng], baseB + boff[ng][ks]);
#pragma unroll
            for (int mi = 0; mi < 4; mi++)
#pragma unroll
                for (int nf = 0; nf < 8; nf++)
                    mma16816(acc[mi][nf], af[mi], bfr[nf >> 1][nf & 1], bfr[nf >> 1][(nf & 1) + 2]);
        }
        if (t + 3 < KT) load_tile(t + 3);
        else cpcommit();   // empty group keeps wait_group accounting exact
    }

    // epilogue: fragment (mi,nf): c0,c1 at (m, n..n+1), c2,c3 at (m+8, n..n+1)
#pragma unroll
    for (int mi = 0; mi < 4; mi++) {
#pragma unroll
        for (int nf = 0; nf < 8; nf++) {
            int m0 = row0 + wm + mi * 16 + (lane >> 2);
            int n = col0 + wn + nf * 8 + (lane & 3) * 2;
#pragma unroll
            for (int half = 0; half < 2; half++) {
                int m = m0 + half * 8;
                float v0 = acc[mi][nf][half * 2 + 0];
                float v1 = acc[mi][nf][half * 2 + 1];
                if (EPI == 1) {
                    *reinterpret_cast<float2*>(&C[(size_t)m * Ntot + n]) = make_float2(v0, v1);
                } else {
                    const int bb = m >> 11, nn = m & 2047;
                    const int sect = n >> 9;
                    const int h = (n >> 6) & 7;
                    const int d = n & 63;
                    if (sect == 2) {
                        __nv_bfloat162 hi = __float22bfloat162_rn(make_float2(v0, v1));
                        __nv_bfloat162 lo = __float22bfloat162_rn(
                            make_float2(v0 - __low2float(hi), v1 - __high2float(hi)));
                        size_t vb = ((size_t)((bb * NHEADS + h) * NSEQ) + nn) * DH + d;
                        *reinterpret_cast<__nv_bfloat162*>(&g_vh[vb]) = hi;
                        *reinterpret_cast<__nv_bfloat162*>(&g_vl[vb]) = lo;
                    } else {
                        int ci = (h * NSEQ + nn) * KP + (d >> 1);
                        float c0 = g_cos[ci], s0 = g_sin[ci];
                        float o0 = v0 * c0 - v1 * s0;
                        float o1 = v0 * s0 + v1 * c0;
                        __nv_bfloat162 hi = __float22bfloat162_rn(make_float2(o0, o1));
                        __nv_bfloat162 lo = __float22bfloat162_rn(
                            make_float2(o0 - __low2float(hi), o1 - __high2float(hi)));
                        size_t qb = ((size_t)((bb * NHEADS + h) * NSEQ) + nn) * 128 + d;
                        if (sect == 0) {   // Q: [hi | lo]
                            *reinterpret_cast<__nv_bfloat162*>(&g_qe[qb]) = hi;
                            *reinterpret_cast<__nv_bfloat162*>(&g_qe[qb + 64]) = lo;
                        } else {           // K: [hi | lo]
                            *reinterpret_cast<__nv_bfloat162*>(&g_ke[qb]) = hi;
                            *reinterpret_cast<__nv_bfloat162*>(&g_ke[qb + 64]) = lo;
                        }
                    }
                }
            }
        }
    }
}

// ---------------- bf16x3 split conversions ----------------
__global__ void convA_kernel(const float* __restrict__ src, __nv_bfloat16* __restrict__ dst, int M) {
    int i = blockIdx.x * blockDim.x + threadIdx.x;
    if (i >= M * 128) return;
    int row = i >> 7, c4 = (i & 127) * 4;
    float4 v = *reinterpret_cast<const float4*>(&src[(size_t)row * DMODEL + c4]);
    __nv_bfloat16 h0 = __float2bfloat16(v.x), h1 = __float2bfloat16(v.y);
    __nv_bfloat16 h2 = __float2bfloat16(v.z), h3 = __float2bfloat16(v.w);
    __nv_bfloat16 l0 = __float2bfloat16(v.x - __bfloat162float(h0));
    __nv_bfloat16 l1 = __float2bfloat16(v.y - __bfloat162float(h1));
    __nv_bfloat16 l2 = __float2bfloat16(v.z - __bfloat162float(h2));
    __nv_bfloat16 l3 = __float2bfloat16(v.w - __bfloat162float(h3));
    size_t base = (size_t)row * KEXP + c4;
    __nv_bfloat162* d0 = reinterpret_cast<__nv_bfloat162*>(&dst[base]);
    __nv_bfloat162* d1 = reinterpret_cast<__nv_bfloat162*>(&dst[base + 512]);
    __nv_bfloat162* d2 = reinterpret_cast<__nv_bfloat162*>(&dst[base + 1024]);
    d0[0] = __nv_bfloat162(h0, h1); d0[1] = __nv_bfloat162(h2, h3);
    d1[0] = __nv_bfloat162(l0, l1); d1[1] = __nv_bfloat162(l2, l3);
    d2[0] = __nv_bfloat162(h0, h1); d2[1] = __nv_bfloat162(h2, h3);
}

__global__ void convB_kernel(const float* __restrict__ w, __nv_bfloat16* __restrict__ dst, int N) {
    int i = blockIdx.x * blockDim.x + threadIdx.x;
    if (i >= N * DMODEL) return;
    int k = i & 511, n = i >> 9;
    float v = w[(size_t)k * N + n];
    __nv_bfloat16 hi = __float2bfloat16(v);
    __nv_bfloat16 lo = __float2bfloat16(v - __bfloat162float(hi));
    size_t base = (size_t)n * KEXP + k;
    dst[base] = hi;
    dst[base + 512] = hi;
    dst[base + 1024] = lo;
}

// ---------------- theta / cos / sin / per-key bias ----------------
__global__ void prep_kernel(const float* __restrict__ log_scale,
                            const float* __restrict__ log_lambda_sigma) {
    int idx = blockIdx.x * blockDim.x + threadIdx.x;
    if (idx >= NHEADS * NSEQ) return;
    int h = idx / NSEQ;
    int n = idx % NSEQ;
    float sc = expf(log_scale[h]);
    float lam = expf(log_lambda_sigma[h]);
    float tau = log1pf((float)n);
    float ssum = 0.0f;
#pragma unroll
    for (int p = 0; p < KP; p++) {
        float g = c_zim[p] / c_zim[0];
        float th = tau * g * sc;
        g_cos[idx * KP + p] = cosf(th);
        g_sin[idx * KP + p] = sinf(th);
        ssum += floorf(th / TAU_F);
    }
    g_bias[idx] = lam * ssum * (1.0f / KP);
}

// ---------------- tensor-core flash attention (full first-order compensation) ----
// Q = [qh|ql], K = [kh|kl] (128 cols, pitch 272B); Vh/Vl 64 cols (pitch 144B).
// QK: s = qh*kh + ql*kh + qh*kl  (lo*lo dropped).
// PV: o += Ph*Vh + Pl*Vh + Ph*Vl (lo*lo dropped).
#define QPITCH 272
#define VPITCH 144
#define QOFF   0
#define QSZ    (128 * QPITCH)                      // 34816
#define KSZ    (64 * QPITCH)                       // 17408
#define STSZ   (KSZ + 2 * 64 * VPITCH + 256)       // 36096
#define KOFF(s)  (QSZ + (s) * STSZ)
#define VHOFF(s) (KOFF(s) + KSZ)
#define VLOFF(s) (VHOFF(s) + 64 * VPITCH)
#define BOFF(s)  (VLOFF(s) + 64 * VPITCH)
#define ATT_SMEM (QSZ + 2 * STSZ)                  // 107008

__global__ __launch_bounds__(256, 2) void attn3_kernel() {
    extern __shared__ char smc[];
    const uint32_t smb = smem_u32(smc);
    const int tid = threadIdx.x;
    const int lane = tid & 31;
    const int wid = tid >> 5;
    const int bh = blockIdx.x;
    const int h = bh & (NHEADS - 1);
    const int b = bh >> 3;
    const int qbase = (15 - (int)blockIdx.y) << 7;
    const int ntiles = (qbase >> 6) + 2;

    const __nv_bfloat16* qe = g_qe + (size_t)bh * NSEQ * 128;
    const __nv_bfloat16* ke = g_ke + (size_t)bh * NSEQ * 128;
    const __nv_bfloat16* vh = g_vh + (size_t)bh * NSEQ * DH;
    const __nv_bfloat16* vl = g_vl + (size_t)bh * NSEQ * DH;
    const float* bp = g_bias + h * NSEQ;

    // Q tile: 128 rows x 256B
    for (int i = tid; i < 2048; i += 256) {
        int r = i >> 4, c = i & 15;
        cpasync16(smb + QOFF + r * QPITCH + c * 16, qe + (size_t)(qbase + r) * 128 + c * 8);
    }
    auto load_tile = [&](int t, int st) {
        int jg = t << 6;
#pragma unroll
        for (int q = 0; q < 4; q++) {           // K: 64 rows x 256B
            int i = q * 256 + tid, r = i >> 4, c = i & 15;
            cpasync16(smb + KOFF(st) + r * QPITCH + c * 16, ke + (size_t)(jg + r) * 128 + c * 8);
        }
#pragma unroll
        for (int q = 0; q < 2; q++) {           // Vh/Vl: 64 rows x 128B
            int i = q * 256 + tid, r = i >> 3, c = i & 7;
            cpasync16(smb + VHOFF(st) + r * VPITCH + c * 16, vh + (size_t)(jg + r) * DH + c * 8);
            cpasync16(smb + VLOFF(st) + r * VPITCH + c * 16, vl + (size_t)(jg + r) * DH + c * 8);
        }
        if (tid < 16) cpasync16(smb + BOFF(st) + tid * 16, bp + jg + tid * 4);
    };
    load_tile(0, 0);
    cpcommit();
    load_tile(1, 1);
    cpcommit();

    const uint32_t qaddr = smb + QOFF + (wid * 16 + (lane & 15)) * QPITCH + (lane >> 4) * 16;
    const uint32_t klocal = (uint32_t)((lane & 15) * QPITCH + (lane >> 4) * 16);
    const uint32_t vlocal = (uint32_t)((lane & 15) * VPITCH + (lane >> 4) * 16);

    float o[8][4];
#pragma unroll
    for (int i = 0; i < 8; i++)
#pragma unroll
        for (int q = 0; q < 4; q++) o[i][q] = 0.0f;
    float m0 = -INFINITY, m1 = -INFINITY, l0 = 0.0f, l1 = 0.0f;
    const int qm0 = qbase + wid * 16 + (lane >> 2);
    const int qm1 = qm0 + 8;

    for (int t = 0; t < ntiles; t++) {
        if (t < ntiles - 1) cpwait<1>(); else cpwait<0>();
        __syncthreads();
        const int st = t & 1;
        const int jg = t << 6;

        // ---- S = qh*kh + ql*kh + qh*kl ----
        float s[8][4];
#pragma unroll
        for (int i = 0; i < 8; i++)
#pragma unroll
            for (int q = 0; q < 4; q++) s[i][q] = 0.0f;
        const uint32_t kb = smb + KOFF(st);
#pragma unroll
        for (int ks = 0; ks < 4; ks++) {
            uint32_t ahi[4], alo[4];
            ldsm4(ahi, qaddr + ks * 32);
            ldsm4(alo, qaddr + 128 + ks * 32);
#pragma unroll
            for (int ng = 0; ng < 4; ng++) {
                uint32_t bh2[4], bl2[4];
                ldsm4(bh2, kb + klocal + ng * (16 * QPITCH) + ks * 32);
                ldsm4(bl2, kb + klocal + ng * (16 * QPITCH) + 128 + ks * 32);
                mma16816(s[2 * ng],     ahi, bh2[0], bh2[2]);
                mma16816(s[2 * ng + 1], ahi, bh2[1], bh2[3]);
                mma16816(s[2 * ng],     alo, bh2[0], bh2[2]);
                mma16816(s[2 * ng + 1], alo, bh2[1], bh2[3]);
                mma16816(s[2 * ng],     ahi, bl2[0], bl2[2]);
                mma16816(s[2 * ng + 1], ahi, bl2[1], bl2[3]);
            }
        }

        const bool masked = (t >= ntiles - 2);
#pragma unroll
        for (int nf = 0; nf < 8; nf++) {
            int col = jg + nf * 8 + ((lane & 3) << 1);
            float2 bj = *reinterpret_cast<const float2*>(smc + BOFF(st) + (nf * 8 + ((lane & 3) << 1)) * 4);
            s[nf][0] = s[nf][0] * 0.125f + bj.x;
            s[nf][1] = s[nf][1] * 0.125f + bj.y;
            s[nf][2] = s[nf][2] * 0.125f + bj.x;
            s[nf][3] = s[nf][3] * 0.125f + bj.y;
            if (masked) {
                if (col > qm0)     s[nf][0] = -INFINITY;
                if (col + 1 > qm0) s[nf][1] = -INFINITY;
                if (col > qm1)     s[nf][2] = -INFINITY;
                if (col + 1 > qm1) s[nf][3] = -INFINITY;
            }
        }

        float mx0 = -INFINITY, mx1 = -INFINITY;
#pragma unroll
        for (int nf = 0; nf < 8; nf++) {
            mx0 = fmaxf(mx0, fmaxf(s[nf][0], s[nf][1]));
            mx1 = fmaxf(mx1, fmaxf(s[nf][2], s[nf][3]));
        }
        mx0 = fmaxf(mx0, __shfl_xor_sync(0xffffffffu, mx0, 1));
        mx0 = fmaxf(mx0, __shfl_xor_sync(0xffffffffu, mx0, 2));
        mx1 = fmaxf(mx1, __shfl_xor_sync(0xffffffffu, mx1, 1));
        mx1 = fmaxf(mx1, __shfl_xor_sync(0xffffffffu, mx1, 2));
        float mn0 = fmaxf(m0, mx0), mn1 = fmaxf(m1, mx1);
        float corr0 = __expf(m0 - mn0), corr1 = __expf(m1 - mn1);
        m0 = mn0; m1 = mn1;
        float ps0 = 0.0f, ps1 = 0.0f;
#pragma unroll
        for (int nf = 0; nf < 8; nf++) {
            s[nf][0] = __expf(s[nf][0] - mn0);
            s[nf][1] = __expf(s[nf][1] - mn0);
            s[nf][2] = __expf(s[nf][2] - mn1);
            s[nf][3] = __expf(s[nf][3] - mn1);
            ps0 += s[nf][0] + s[nf][1];
            ps1 += s[nf][2] + s[nf][3];
        }
        ps0 += __shfl_xor_sync(0xffffffffu, ps0, 1);
        ps0 += __shfl_xor_sync(0xffffffffu, ps0, 2);
        ps1 += __shfl_xor_sync(0xffffffffu, ps1, 1);
        ps1 += __shfl_xor_sync(0xffffffffu, ps1, 2);
        l0 = l0 * corr0 + ps0;
        l1 = l1 * corr1 + ps1;
#pragma unroll
        for (int nf = 0; nf < 8; nf++) {
            o[nf][0] *= corr0; o[nf][1] *= corr0;
            o[nf][2] *= corr1; o[nf][3] *= corr1;
        }

        // ---- O += Ph*Vh + Pl*Vh + Ph*Vl ----
        const uint32_t vhb = smb + VHOFF(st);
        const uint32_t vlb = smb + VLOFF(st);
#pragma unroll
        for (int ks2 = 0; ks2 < 4; ks2++) {
            const int f0 = 2 * ks2, f1 = 2 * ks2 + 1;
            __nv_bfloat162 h0 = __float22bfloat162_rn(make_float2(s[f0][0], s[f0][1]));
            __nv_bfloat162 h1 = __float22bfloat162_rn(make_float2(s[f0][2], s[f0][3]));
            __nv_bfloat162 h2 = __float22bfloat162_rn(make_float2(s[f1][0], s[f1][1]));
            __nv_bfloat162 h3 = __float22bfloat162_rn(make_float2(s[f1][2], s[f1][3]));
            __nv_bfloat162 e0 = __float22bfloat162_rn(
                make_float2(s[f0][0] - __low2float(h0), s[f0][1] - __high2float(h0)));
            __nv_bfloat162 e1 = __float22bfloat162_rn(
                make_float2(s[f0][2] - __low2float(h1), s[f0][3] - __high2float(h1)));
            __nv_bfloat162 e2 = __float22bfloat162_rn(
                make_float2(s[f1][0] - __low2float(h2), s[f1][1] - __high2float(h2)));
            __nv_bfloat162 e3 = __float22bfloat162_rn(
                make_float2(s[f1][2] - __low2float(h3), s[f1][3] - __high2float(h3)));
            uint32_t ah[4] = {*(uint32_t*)&h0, *(uint32_t*)&h1, *(uint32_t*)&h2, *(uint32_t*)&h3};
            uint32_t al[4] = {*(uint32_t*)&e0, *(uint32_t*)&e1, *(uint32_t*)&e2, *(uint32_t*)&e3};
#pragma unroll
            for (int dseg = 0; dseg < 4; dseg++) {
                uint32_t bhf[4], blf[4];
                ldsm4t(bhf, vhb + ks2 * (16 * VPITCH) + vlocal + dseg * 32);
                ldsm4t(blf, vlb + ks2 * (16 * VPITCH) + vlocal + dseg * 32);
                mma16816(o[2 * dseg],     ah, bhf[0], bhf[1]);
                mma16816(o[2 * dseg + 1], ah, bhf[2], bhf[3]);
                mma16816(o[2 * dseg],     al, bhf[0], bhf[1]);
                mma16816(o[2 * dseg + 1], al, bhf[2], bhf[3]);
                mma16816(o[2 * dseg],     ah, blf[0], blf[1]);
                mma16816(o[2 * dseg + 1], ah, blf[2], blf[3]);
            }
        }

        __syncthreads();
        if (t + 2 < ntiles) { load_tile(t + 2, st); cpcommit(); }
    }

    const float inv0 = 1.0f / l0, inv1 = 1.0f / l1;
#pragma unroll
    for (int nf = 0; nf < 8; nf++) {
        int col = h * DH + nf * 8 + ((lane & 3) << 1);
        *reinterpret_cast<float2*>(&g_att[(size_t)(b * NSEQ + qm0) * DMODEL + col]) =
            make_float2(o[nf][0] * inv0, o[nf][1] * inv0);
        *reinterpret_cast<float2*>(&g_att[(size_t)(b * NSEQ + qm1) * DMODEL + col]) =
            make_float2(o[nf][2] * inv1, o[nf][3] * inv1);
    }
}

// ---------------- launch ----------------
extern "C" void kernel_launch(void* const* d_in, const int* in_sizes, int n_in,
                              void* d_out, int out_size) {
    const float* x      = (const float*)d_in[0];
    const float* w_qkv  = (const float*)d_in[1];
    const float* w_o    = (const float*)d_in[2];
    const float* lscale = (const float*)d_in[3];
    const float* lls    = (const float*)d_in[4];
    float* out = (float*)d_out;

    float* att;
    __nv_bfloat16 *aexp, *bexp, *bexp2;
    cudaGetSymbolAddress((void**)&att, g_att);
    cudaGetSymbolAddress((void**)&aexp, g_aexp);
    cudaGetSymbolAddress((void**)&bexp, g_bexp);
    cudaGetSymbolAddress((void**)&bexp2, g_bexp2);

    const int M = BATCH * NSEQ;   // 4096
    cudaFuncSetAttribute(attn3_kernel, cudaFuncAttributeMaxDynamicSharedMemorySize, ATT_SMEM);
    cudaFuncSetAttribute(mmagemm<0>, cudaFuncAttributeMaxDynamicSharedMemorySize, GEMM_SMEM);
    cudaFuncSetAttribute(mmagemm<1>, cudaFuncAttributeMaxDynamicSharedMemorySize, GEMM_SMEM);

    // 1) theta/cos/sin + per-key bias (needed by GEMM1 epilogue + attention)
    prep_kernel<<<(NHEADS * NSEQ + 127) / 128, 128>>>(lscale, lls);

    // 2) bf16x3 conversions for QKV GEMM
    convA_kernel<<<(M * 128 + 255) / 256, 256>>>(x, aexp, M);
    convB_kernel<<<(3 * DMODEL * DMODEL + 255) / 256, 256>>>(w_qkv, bexp, 3 * DMODEL);

    // 3) QKV projection; epilogue rotates and emits split-bf16 Q/K/Vh/Vl
    mmagemm<0><<<dim3(3 * DMODEL / 128, M / 128), 128, GEMM_SMEM>>>(aexp, bexp, nullptr, 3 * DMODEL);

    // 4) tensor-core flash attention with per-key bias
    attn3_kernel<<<dim3(BATCH * NHEADS, NSEQ / 128), 256, ATT_SMEM>>>();

    // 5) output projection
    convA_kernel<<<(M * 128 + 255) / 256, 256>>>(att, aexp, M);
    convB_kernel<<<(DMODEL * DMODEL + 255) / 256, 256>>>(w_o, bexp2, DMODEL);
    mmagemm<1><<<dim3(DMODEL / 128, M / 128), 128, GEMM_SMEM>>>(aexp, bexp2, out, DMODEL);
}

// round 10
// speedup vs baseline: 1.1202x; 1.1202x over previous
#include <cuda_runtime.h>
#include <cuda_bf16.h>
#include <cstdint>
#include <math.h>

#define BATCH   2
#define NSEQ    2048
#define DMODEL  512
#define NHEADS  8
#define DH      64
#define KP      32
#define KEXP    1536
#define TAU_F   6.283185307179586f

// ---------------- scratch (static device memory; no allocations) ----------------
__device__ __nv_bfloat16 g_qe[(size_t)BATCH * NHEADS * NSEQ * 128];  // [qh|ql]
__device__ __nv_bfloat16 g_ke[(size_t)BATCH * NHEADS * NSEQ * 128];  // [kh|kl]
__device__ __nv_bfloat16 g_vh[(size_t)BATCH * NHEADS * NSEQ * DH];
__device__ __nv_bfloat16 g_vl[(size_t)BATCH * NHEADS * NSEQ * DH];
__device__ float g_cos[NHEADS * NSEQ * KP];
__device__ float g_sin[NHEADS * NSEQ * KP];
__device__ float g_bias[NHEADS * NSEQ];                             // lam*S_n/KP per head
__device__ __nv_bfloat16 g_aexp[(size_t)BATCH * NSEQ * KEXP];       // A' 4096x1536
__device__ __nv_bfloat16 g_bexp[(size_t)3 * DMODEL * KEXP];         // B' 1536x1536
__device__ __nv_bfloat16 g_bexp2[(size_t)DMODEL * KEXP];            // B2' 512x1536

__constant__ float c_zim[KP] = {
    14.134725142f, 21.022039639f, 25.01085758f,  30.424876126f,
    32.935061588f, 37.586178159f, 40.918719012f, 43.327073281f,
    48.005150881f, 49.773832478f, 52.970321478f, 56.446247697f,
    59.347044003f, 60.831778525f, 65.112544048f, 67.079810529f,
    69.546401711f, 72.067157674f, 75.704690699f, 77.144840069f,
    79.33737502f,  82.910380854f, 84.735492981f, 87.425274613f,
    88.809111208f, 92.491899271f, 94.651344041f, 95.870634228f,
    98.831194218f, 101.317851006f, 103.72553804f, 105.446623052f};

// ---------------- warp-MMA / async helpers (portable sm_80+ path) ----------------
__device__ __forceinline__ uint32_t smem_u32(const void* p) {
    uint32_t a;
    asm("{ .reg .u64 t; cvta.to.shared.u64 t, %1; cvt.u32.u64 %0, t; }" : "=r"(a) : "l"(p));
    return a;
}
__device__ __forceinline__ void ldsm4(uint32_t* r, uint32_t a) {
    asm volatile("ldmatrix.sync.aligned.m8n8.x4.shared.b16 {%0,%1,%2,%3}, [%4];"
                 : "=r"(r[0]), "=r"(r[1]), "=r"(r[2]), "=r"(r[3]) : "r"(a));
}
__device__ __forceinline__ void ldsm4t(uint32_t* r, uint32_t a) {
    asm volatile("ldmatrix.sync.aligned.m8n8.x4.trans.shared.b16 {%0,%1,%2,%3}, [%4];"
                 : "=r"(r[0]), "=r"(r[1]), "=r"(r[2]), "=r"(r[3]) : "r"(a));
}
__device__ __forceinline__ void mma16816(float* c, const uint32_t* a, uint32_t b0, uint32_t b1) {
    asm volatile("mma.sync.aligned.m16n8k16.row.col.f32.bf16.bf16.f32 "
                 "{%0,%1,%2,%3}, {%4,%5,%6,%7}, {%8,%9}, {%0,%1,%2,%3};"
                 : "+f"(c[0]), "+f"(c[1]), "+f"(c[2]), "+f"(c[3])
                 : "r"(a[0]), "r"(a[1]), "r"(a[2]), "r"(a[3]), "r"(b0), "r"(b1));
}
__device__ __forceinline__ void cpasync16(uint32_t dst, const void* src) {
    asm volatile("cp.async.cg.shared.global [%0], [%1], 16;" :: "r"(dst), "l"(src));
}
__device__ __forceinline__ void cpcommit() {
    asm volatile("cp.async.commit_group;");
}
template <int N>
__device__ __forceinline__ void cpwait() {
    asm volatile("cp.async.wait_group %0;" :: "n"(N));
}

// ---------------- bf16 mma GEMM: 8 warps x (64x32), fragment-pipelined ----------
// C[M,Ntot] = A'[M,1536] @ B'[Ntot,1536]^T, 128x128 CTA tile, K-tiles of 32.
#define KT (KEXP / 32)
#define SWZ(r, bc) ((uint32_t)((r) * 64 + ((bc) ^ ((((r) >> 1) & 3) << 4))))
#define GSTAGES 4
#define GSTG_SZ 16384               // A(8KB) + B(8KB) per stage
#define GEMM_SMEM (GSTAGES * GSTG_SZ)

template <int EPI>
__global__ __launch_bounds__(256, 2) void mmagemm(const __nv_bfloat16* __restrict__ A,
                                                  const __nv_bfloat16* __restrict__ Bm,
                                                  float* __restrict__ C, int Ntot) {
    extern __shared__ char gsm[];
    const uint32_t sbase = smem_u32(gsm);

    const int tid = threadIdx.x;
    const int lane = tid & 31;
    const int wid = tid >> 5;
    const int wm = (wid & 1) * 64;
    const int wn = (wid >> 1) * 32;
    const int row0 = blockIdx.y * 128;
    const int col0 = blockIdx.x * 128;

    // ldmatrix per-lane offsets
    const int lr = (lane & 7) + ((lane >> 3) & 1) * 8;
    const int kh = (lane >> 4) * 16;
    uint32_t aoff[4][2], boff[2][2];
#pragma unroll
    for (int mi = 0; mi < 4; mi++)
#pragma unroll
        for (int ks = 0; ks < 2; ks++) aoff[mi][ks] = SWZ(wm + mi * 16 + lr, ks * 32 + kh);
#pragma unroll
    for (int g = 0; g < 2; g++)
#pragma unroll
        for (int ks = 0; ks < 2; ks++) boff[g][ks] = SWZ(wn + g * 16 + lr, ks * 32 + kh);

    // cp.async mapping: thread covers rows r_ld0 and r_ld0+64, 16B each
    const int r_ld0 = tid >> 2, cu_ld = tid & 3;
    const int r_ld1 = r_ld0 + 64;
    const uint32_t so0 = SWZ(r_ld0, cu_ld * 16);
    const uint32_t so1 = SWZ(r_ld1, cu_ld * 16);
    const __nv_bfloat16* a0p = &A[(size_t)(row0 + r_ld0) * KEXP + cu_ld * 8];
    const __nv_bfloat16* a1p = &A[(size_t)(row0 + r_ld1) * KEXP + cu_ld * 8];
    const __nv_bfloat16* b0p = &Bm[(size_t)(col0 + r_ld0) * KEXP + cu_ld * 8];
    const __nv_bfloat16* b1p = &Bm[(size_t)(col0 + r_ld1) * KEXP + cu_ld * 8];

    auto load_tile = [&](int t) {
        const uint32_t st = sbase + (uint32_t)((t & (GSTAGES - 1)) * GSTG_SZ);
        const int k0 = t * 32;
        cpasync16(st + so0, a0p + k0);
        cpasync16(st + so1, a1p + k0);
        cpasync16(st + 8192 + so0, b0p + k0);
        cpasync16(st + 8192 + so1, b1p + k0);
        cpcommit();
    };
    load_tile(0);
    load_tile(1);
    load_tile(2);

    float acc[4][4][4];
#pragma unroll
    for (int mi = 0; mi < 4; mi++)
#pragma unroll
        for (int ni = 0; ni < 4; ni++)
#pragma unroll
            for (int q = 0; q < 4; q++) acc[mi][ni][q] = 0.0f;

    uint32_t af[2][4][4], bfr[2][2][4];

    // tiles 0 and 1 are resident after this wait+barrier
    cpwait<1>();
    __syncthreads();
    // prefetch (tile 0, ks 0) into buffer 0
    {
        const uint32_t bA = sbase;
#pragma unroll
        for (int mi = 0; mi < 4; mi++) ldsm4(af[0][mi], bA + aoff[mi][0]);
#pragma unroll
        for (int g = 0; g < 2; g++) ldsm4(bfr[0][g], bA + 8192 + boff[g][0]);
    }

    for (int t = 0; t < KT; t++) {
        const uint32_t bA = sbase + (uint32_t)((t & (GSTAGES - 1)) * GSTG_SZ);
        const int tn = (t + 1 < KT) ? t + 1 : t;   // clamp: re-read (unused) on last iter
        const uint32_t bA1 = sbase + (uint32_t)((tn & (GSTAGES - 1)) * GSTG_SZ);

        // issue ldsm for ks=1 (buffer 1), then MMA on buffer 0 — latency overlapped
#pragma unroll
        for (int mi = 0; mi < 4; mi++) ldsm4(af[1][mi], bA + aoff[mi][1]);
#pragma unroll
        for (int g = 0; g < 2; g++) ldsm4(bfr[1][g], bA + 8192 + boff[g][1]);
#pragma unroll
        for (int mi = 0; mi < 4; mi++)
#pragma unroll
            for (int ni = 0; ni < 4; ni++)
                mma16816(acc[mi][ni], af[0][mi], bfr[0][ni >> 1][ni & 1], bfr[0][ni >> 1][(ni & 1) + 2]);

        // prefetch (tile t+1, ks 0) into buffer 0, then MMA on buffer 1
#pragma unroll
        for (int mi = 0; mi < 4; mi++) ldsm4(af[0][mi], bA1 + aoff[mi][0]);
#pragma unroll
        for (int g = 0; g < 2; g++) ldsm4(bfr[0][g], bA1 + 8192 + boff[g][0]);
#pragma unroll
        for (int mi = 0; mi < 4; mi++)
#pragma unroll
            for (int ni = 0; ni < 4; ni++)
                mma16816(acc[mi][ni], af[1][mi], bfr[1][ni >> 1][ni & 1], bfr[1][ni >> 1][(ni & 1) + 2]);

        if (t + 3 < KT) load_tile(t + 3);
        else cpcommit();   // empty group keeps wait_group accounting exact
        cpwait<1>();       // tiles t+1, t+2 resident for next iter
        __syncthreads();
    }

    // epilogue: fragment (mi,ni): c0,c1 at (m, n..n+1), c2,c3 at (m+8, n..n+1)
#pragma unroll
    for (int mi = 0; mi < 4; mi++) {
#pragma unroll
        for (int ni = 0; ni < 4; ni++) {
            int m0 = row0 + wm + mi * 16 + (lane >> 2);
            int n = col0 + wn + ni * 8 + (lane & 3) * 2;
#pragma unroll
            for (int half = 0; half < 2; half++) {
                int m = m0 + half * 8;
                float v0 = acc[mi][ni][half * 2 + 0];
                float v1 = acc[mi][ni][half * 2 + 1];
                if (EPI == 1) {
                    *reinterpret_cast<float2*>(&C[(size_t)m * Ntot + n]) = make_float2(v0, v1);
                } else {
                    const int bb = m >> 11, nn = m & 2047;
                    const int sect = n >> 9;
                    const int h = (n >> 6) & 7;
                    const int d = n & 63;
                    if (sect == 2) {
                        __nv_bfloat162 hi = __float22bfloat162_rn(make_float2(v0, v1));
                        __nv_bfloat162 lo = __float22bfloat162_rn(
                            make_float2(v0 - __low2float(hi), v1 - __high2float(hi)));
                        size_t vb = ((size_t)((bb * NHEADS + h) * NSEQ) + nn) * DH + d;
                        *reinterpret_cast<__nv_bfloat162*>(&g_vh[vb]) = hi;
                        *reinterpret_cast<__nv_bfloat162*>(&g_vl[vb]) = lo;
                    } else {
                        int ci = (h * NSEQ + nn) * KP + (d >> 1);
                        float c0 = g_cos[ci], s0 = g_sin[ci];
                        float o0 = v0 * c0 - v1 * s0;
                        float o1 = v0 * s0 + v1 * c0;
                        __nv_bfloat162 hi = __float22bfloat162_rn(make_float2(o0, o1));
                        __nv_bfloat162 lo = __float22bfloat162_rn(
                            make_float2(o0 - __low2float(hi), o1 - __high2float(hi)));
                        size_t qb = ((size_t)((bb * NHEADS + h) * NSEQ) + nn) * 128 + d;
                        if (sect == 0) {   // Q: [hi | lo]
                            *reinterpret_cast<__nv_bfloat162*>(&g_qe[qb]) = hi;
                            *reinterpret_cast<__nv_bfloat162*>(&g_qe[qb + 64]) = lo;
                        } else {           // K: [hi | lo]
                            *reinterpret_cast<__nv_bfloat162*>(&g_ke[qb]) = hi;
                            *reinterpret_cast<__nv_bfloat162*>(&g_ke[qb + 64]) = lo;
                        }
                    }
                }
            }
        }
    }
}

// ---------------- bf16x3 split conversions ----------------
__global__ void convA_kernel(const float* __restrict__ src, __nv_bfloat16* __restrict__ dst, int M) {
    int i = blockIdx.x * blockDim.x + threadIdx.x;
    if (i >= M * 128) return;
    int row = i >> 7, c4 = (i & 127) * 4;
    float4 v = *reinterpret_cast<const float4*>(&src[(size_t)row * DMODEL + c4]);
    __nv_bfloat16 h0 = __float2bfloat16(v.x), h1 = __float2bfloat16(v.y);
    __nv_bfloat16 h2 = __float2bfloat16(v.z), h3 = __float2bfloat16(v.w);
    __nv_bfloat16 l0 = __float2bfloat16(v.x - __bfloat162float(h0));
    __nv_bfloat16 l1 = __float2bfloat16(v.y - __bfloat162float(h1));
    __nv_bfloat16 l2 = __float2bfloat16(v.z - __bfloat162float(h2));
    __nv_bfloat16 l3 = __float2bfloat16(v.w - __bfloat162float(h3));
    size_t base = (size_t)row * KEXP + c4;
    __nv_bfloat162* d0 = reinterpret_cast<__nv_bfloat162*>(&dst[base]);
    __nv_bfloat162* d1 = reinterpret_cast<__nv_bfloat162*>(&dst[base + 512]);
    __nv_bfloat162* d2 = reinterpret_cast<__nv_bfloat162*>(&dst[base + 1024]);
    d0[0] = __nv_bfloat162(h0, h1); d0[1] = __nv_bfloat162(h2, h3);
    d1[0] = __nv_bfloat162(l0, l1); d1[1] = __nv_bfloat162(l2, l3);
    d2[0] = __nv_bfloat162(h0, h1); d2[1] = __nv_bfloat162(h2, h3);
}

__global__ void convB_kernel(const float* __restrict__ w, __nv_bfloat16* __restrict__ dst, int N) {
    int i = blockIdx.x * blockDim.x + threadIdx.x;
    if (i >= N * DMODEL) return;
    int k = i & 511, n = i >> 9;
    float v = w[(size_t)k * N + n];
    __nv_bfloat16 hi = __float2bfloat16(v);
    __nv_bfloat16 lo = __float2bfloat16(v - __bfloat162float(hi));
    size_t base = (size_t)n * KEXP + k;
    dst[base] = hi;
    dst[base + 512] = hi;
    dst[base + 1024] = lo;
}

// ---------------- theta / cos / sin / per-key bias ----------------
__global__ void prep_kernel(const float* __restrict__ log_scale,
                            const float* __restrict__ log_lambda_sigma) {
    int idx = blockIdx.x * blockDim.x + threadIdx.x;
    if (idx >= NHEADS * NSEQ) return;
    int h = idx / NSEQ;
    int n = idx % NSEQ;
    float sc = expf(log_scale[h]);
    float lam = expf(log_lambda_sigma[h]);
    float tau = log1pf((float)n);
    float ssum = 0.0f;
#pragma unroll
    for (int p = 0; p < KP; p++) {
        float g = c_zim[p] / c_zim[0];
        float th = tau * g * sc;
        g_cos[idx * KP + p] = cosf(th);
        g_sin[idx * KP + p] = sinf(th);
        ssum += floorf(th / TAU_F);
    }
    g_bias[idx] = lam * ssum * (1.0f / KP);
}

// ---------------- tensor-core flash attention (full first-order compensation) ----
// Q = [qh|ql], K = [kh|kl] (128 cols, pitch 272B); Vh/Vl 64 cols (pitch 144B).
// QK: s = qh*kh + ql*kh + qh*kl  (lo*lo dropped).
// PV: o += Ph*Vh + Pl*Vh + Ph*Vl (lo*lo dropped).
// Epilogue writes the bf16x3-split attention output straight into g_aexp.
#define QPITCH 272
#define VPITCH 144
#define QOFF   0
#define QSZ    (128 * QPITCH)                      // 34816
#define KSZ    (64 * QPITCH)                       // 17408
#define STSZ   (KSZ + 2 * 64 * VPITCH + 256)       // 36096
#define KOFF(s)  (QSZ + (s) * STSZ)
#define VHOFF(s) (KOFF(s) + KSZ)
#define VLOFF(s) (VHOFF(s) + 64 * VPITCH)
#define BOFF(s)  (VLOFF(s) + 64 * VPITCH)
#define ATT_SMEM (QSZ + 2 * STSZ)                  // 107008

__global__ __launch_bounds__(256, 2) void attn3_kernel() {
    extern __shared__ char smc[];
    const uint32_t smb = smem_u32(smc);
    const int tid = threadIdx.x;
    const int lane = tid & 31;
    const int wid = tid >> 5;
    const int bh = blockIdx.x;
    const int h = bh & (NHEADS - 1);
    const int b = bh >> 3;
    const int qbase = (15 - (int)blockIdx.y) << 7;
    const int ntiles = (qbase >> 6) + 2;

    const __nv_bfloat16* qe = g_qe + (size_t)bh * NSEQ * 128;
    const __nv_bfloat16* ke = g_ke + (size_t)bh * NSEQ * 128;
    const __nv_bfloat16* vh = g_vh + (size_t)bh * NSEQ * DH;
    const __nv_bfloat16* vl = g_vl + (size_t)bh * NSEQ * DH;
    const float* bp = g_bias + h * NSEQ;

    // Q tile: 128 rows x 256B
    for (int i = tid; i < 2048; i += 256) {
        int r = i >> 4, c = i & 15;
        cpasync16(smb + QOFF + r * QPITCH + c * 16, qe + (size_t)(qbase + r) * 128 + c * 8);
    }
    auto load_tile = [&](int t, int st) {
        int jg = t << 6;
#pragma unroll
        for (int q = 0; q < 4; q++) {           // K: 64 rows x 256B
            int i = q * 256 + tid, r = i >> 4, c = i & 15;
            cpasync16(smb + KOFF(st) + r * QPITCH + c * 16, ke + (size_t)(jg + r) * 128 + c * 8);
        }
#pragma unroll
        for (int q = 0; q < 2; q++) {           // Vh/Vl: 64 rows x 128B
            int i = q * 256 + tid, r = i >> 3, c = i & 7;
            cpasync16(smb + VHOFF(st) + r * VPITCH + c * 16, vh + (size_t)(jg + r) * DH + c * 8);
            cpasync16(smb + VLOFF(st) + r * VPITCH + c * 16, vl + (size_t)(jg + r) * DH + c * 8);
        }
        if (tid < 16) cpasync16(smb + BOFF(st) + tid * 16, bp + jg + tid * 4);
    };
    load_tile(0, 0);
    cpcommit();
    load_tile(1, 1);
    cpcommit();

    const uint32_t qaddr = smb + QOFF + (wid * 16 + (lane & 15)) * QPITCH + (lane >> 4) * 16;
    const uint32_t klocal = (uint32_t)((lane & 15) * QPITCH + (lane >> 4) * 16);
    const uint32_t vlocal = (uint32_t)((lane & 15) * VPITCH + (lane >> 4) * 16);

    float o[8][4];
#pragma unroll
    for (int i = 0; i < 8; i++)
#pragma unroll
        for (int q = 0; q < 4; q++) o[i][q] = 0.0f;
    float m0 = -INFINITY, m1 = -INFINITY, l0 = 0.0f, l1 = 0.0f;
    const int qm0 = qbase + wid * 16 + (lane >> 2);
    const int qm1 = qm0 + 8;

    for (int t = 0; t < ntiles; t++) {
        if (t < ntiles - 1) cpwait<1>(); else cpwait<0>();
        __syncthreads();
        const int st = t & 1;
        const int jg = t << 6;

        // ---- S = qh*kh + ql*kh + qh*kl ----
        float s[8][4];
#pragma unroll
        for (int i = 0; i < 8; i++)
#pragma unroll
            for (int q = 0; q < 4; q++) s[i][q] = 0.0f;
        const uint32_t kb = smb + KOFF(st);
#pragma unroll
        for (int ks = 0; ks < 4; ks++) {
            uint32_t ahi[4], alo[4];
            ldsm4(ahi, qaddr + ks * 32);
            ldsm4(alo, qaddr + 128 + ks * 32);
#pragma unroll
            for (int ng = 0; ng < 4; ng++) {
                uint32_t bh2[4], bl2[4];
                ldsm4(bh2, kb + klocal + ng * (16 * QPITCH) + ks * 32);
                ldsm4(bl2, kb + klocal + ng * (16 * QPITCH) + 128 + ks * 32);
                mma16816(s[2 * ng],     ahi, bh2[0], bh2[2]);
                mma16816(s[2 * ng + 1], ahi, bh2[1], bh2[3]);
                mma16816(s[2 * ng],     alo, bh2[0], bh2[2]);
                mma16816(s[2 * ng + 1], alo, bh2[1], bh2[3]);
                mma16816(s[2 * ng],     ahi, bl2[0], bl2[2]);
                mma16816(s[2 * ng + 1], ahi, bl2[1], bl2[3]);
            }
        }

        const bool masked = (t >= ntiles - 2);
#pragma unroll
        for (int nf = 0; nf < 8; nf++) {
            int col = jg + nf * 8 + ((lane & 3) << 1);
            float2 bj = *reinterpret_cast<const float2*>(smc + BOFF(st) + (nf * 8 + ((lane & 3) << 1)) * 4);
            s[nf][0] = s[nf][0] * 0.125f + bj.x;
            s[nf][1] = s[nf][1] * 0.125f + bj.y;
            s[nf][2] = s[nf][2] * 0.125f + bj.x;
            s[nf][3] = s[nf][3] * 0.125f + bj.y;
            if (masked) {
                if (col > qm0)     s[nf][0] = -INFINITY;
                if (col + 1 > qm0) s[nf][1] = -INFINITY;
                if (col > qm1)     s[nf][2] = -INFINITY;
                if (col + 1 > qm1) s[nf][3] = -INFINITY;
            }
        }

        float mx0 = -INFINITY, mx1 = -INFINITY;
#pragma unroll
        for (int nf = 0; nf < 8; nf++) {
            mx0 = fmaxf(mx0, fmaxf(s[nf][0], s[nf][1]));
            mx1 = fmaxf(mx1, fmaxf(s[nf][2], s[nf][3]));
        }
        mx0 = fmaxf(mx0, __shfl_xor_sync(0xffffffffu, mx0, 1));
        mx0 = fmaxf(mx0, __shfl_xor_sync(0xffffffffu, mx0, 2));
        mx1 = fmaxf(mx1, __shfl_xor_sync(0xffffffffu, mx1, 1));
        mx1 = fmaxf(mx1, __shfl_xor_sync(0xffffffffu, mx1, 2));
        float mn0 = fmaxf(m0, mx0), mn1 = fmaxf(m1, mx1);
        float corr0 = __expf(m0 - mn0), corr1 = __expf(m1 - mn1);
        m0 = mn0; m1 = mn1;
        float ps0 = 0.0f, ps1 = 0.0f;
#pragma unroll
        for (int nf = 0; nf < 8; nf++) {
            s[nf][0] = __expf(s[nf][0] - mn0);
            s[nf][1] = __expf(s[nf][1] - mn0);
            s[nf][2] = __expf(s[nf][2] - mn1);
            s[nf][3] = __expf(s[nf][3] - mn1);
            ps0 += s[nf][0] + s[nf][1];
            ps1 += s[nf][2] + s[nf][3];
        }
        ps0 += __shfl_xor_sync(0xffffffffu, ps0, 1);
        ps0 += __shfl_xor_sync(0xffffffffu, ps0, 2);
        ps1 += __shfl_xor_sync(0xffffffffu, ps1, 1);
        ps1 += __shfl_xor_sync(0xffffffffu, ps1, 2);
        l0 = l0 * corr0 + ps0;
        l1 = l1 * corr1 + ps1;
#pragma unroll
        for (int nf = 0; nf < 8; nf++) {
            o[nf][0] *= corr0; o[nf][1] *= corr0;
            o[nf][2] *= corr1; o[nf][3] *= corr1;
        }

        // ---- O += Ph*Vh + Pl*Vh + Ph*Vl ----
        const uint32_t vhb = smb + VHOFF(st);
        const uint32_t vlb = smb + VLOFF(st);
#pragma unroll
        for (int ks2 = 0; ks2 < 4; ks2++) {
            const int f0 = 2 * ks2, f1 = 2 * ks2 + 1;
            __nv_bfloat162 h0 = __float22bfloat162_rn(make_float2(s[f0][0], s[f0][1]));
            __nv_bfloat162 h1 = __float22bfloat162_rn(make_float2(s[f0][2], s[f0][3]));
            __nv_bfloat162 h2 = __float22bfloat162_rn(make_float2(s[f1][0], s[f1][1]));
            __nv_bfloat162 h3 = __float22bfloat162_rn(make_float2(s[f1][2], s[f1][3]));
            __nv_bfloat162 e0 = __float22bfloat162_rn(
                make_float2(s[f0][0] - __low2float(h0), s[f0][1] - __high2float(h0)));
            __nv_bfloat162 e1 = __float22bfloat162_rn(
                make_float2(s[f0][2] - __low2float(h1), s[f0][3] - __high2float(h1)));
            __nv_bfloat162 e2 = __float22bfloat162_rn(
                make_float2(s[f1][0] - __low2float(h2), s[f1][1] - __high2float(h2)));
            __nv_bfloat162 e3 = __float22bfloat162_rn(
                make_float2(s[f1][2] - __low2float(h3), s[f1][3] - __high2float(h3)));
            uint32_t ah[4] = {*(uint32_t*)&h0, *(uint32_t*)&h1, *(uint32_t*)&h2, *(uint32_t*)&h3};
            uint32_t al[4] = {*(uint32_t*)&e0, *(uint32_t*)&e1, *(uint32_t*)&e2, *(uint32_t*)&e3};
#pragma unroll
            for (int dseg = 0; dseg < 4; dseg++) {
                uint32_t bhf[4], blf[4];
                ldsm4t(bhf, vhb + ks2 * (16 * VPITCH) + vlocal + dseg * 32);
                ldsm4t(blf, vlb + ks2 * (16 * VPITCH) + vlocal + dseg * 32);
                mma16816(o[2 * dseg],     ah, bhf[0], bhf[1]);
                mma16816(o[2 * dseg + 1], ah, bhf[2], bhf[3]);
                mma16816(o[2 * dseg],     al, bhf[0], bhf[1]);
                mma16816(o[2 * dseg + 1], al, bhf[2], bhf[3]);
                mma16816(o[2 * dseg],     ah, blf[0], blf[1]);
                mma16816(o[2 * dseg + 1], ah, blf[2], blf[3]);
            }
        }

        __syncthreads();
        if (t + 2 < ntiles) { load_tile(t + 2, st); cpcommit(); }
    }

    // ---- normalize + write bf16x3 split directly into g_aexp ([hi|lo|hi]) ----
    const float inv0 = 1.0f / l0, inv1 = 1.0f / l1;
#pragma unroll
    for (int nf = 0; nf < 8; nf++) {
        int col = h * DH + nf * 8 + ((lane & 3) << 1);
        size_t r0 = (size_t)(b * NSEQ + qm0) * KEXP + col;
        size_t r1 = (size_t)(b * NSEQ + qm1) * KEXP + col;
        float x0 = o[nf][0] * inv0, y0 = o[nf][1] * inv0;
        float x1 = o[nf][2] * inv1, y1 = o[nf][3] * inv1;
        __nv_bfloat162 h0 = __float22bfloat162_rn(make_float2(x0, y0));
        __nv_bfloat162 l0b = __float22bfloat162_rn(
            make_float2(x0 - __low2float(h0), y0 - __high2float(h0)));
        __nv_bfloat162 h1 = __float22bfloat162_rn(make_float2(x1, y1));
        __nv_bfloat162 l1b = __float22bfloat162_rn(
            make_float2(x1 - __low2float(h1), y1 - __high2float(h1)));
        *reinterpret_cast<__nv_bfloat162*>(&g_aexp[r0]) = h0;
        *reinterpret_cast<__nv_bfloat162*>(&g_aexp[r0 + 512]) = l0b;
        *reinterpret_cast<__nv_bfloat162*>(&g_aexp[r0 + 1024]) = h0;
        *reinterpret_cast<__nv_bfloat162*>(&g_aexp[r1]) = h1;
        *reinterpret_cast<__nv_bfloat162*>(&g_aexp[r1 + 512]) = l1b;
        *reinterpret_cast<__nv_bfloat162*>(&g_aexp[r1 + 1024]) = h1;
    }
}

// ---------------- launch ----------------
extern "C" void kernel_launch(void* const* d_in, const int* in_sizes, int n_in,
                              void* d_out, int out_size) {
    const float* x      = (const float*)d_in[0];
    const float* w_qkv  = (const float*)d_in[1];
    const float* w_o    = (const float*)d_in[2];
    const float* lscale = (const float*)d_in[3];
    const float* lls    = (const float*)d_in[4];
    float* out = (float*)d_out;

    __nv_bfloat16 *aexp, *bexp, *bexp2;
    cudaGetSymbolAddress((void**)&aexp, g_aexp);
    cudaGetSymbolAddress((void**)&bexp, g_bexp);
    cudaGetSymbolAddress((void**)&bexp2, g_bexp2);

    const int M = BATCH * NSEQ;   // 4096
    cudaFuncSetAttribute(attn3_kernel, cudaFuncAttributeMaxDynamicSharedMemorySize, ATT_SMEM);
    cudaFuncSetAttribute(mmagemm<0>, cudaFuncAttributeMaxDynamicSharedMemorySize, GEMM_SMEM);
    cudaFuncSetAttribute(mmagemm<1>, cudaFuncAttributeMaxDynamicSharedMemorySize, GEMM_SMEM);

    // 1) theta/cos/sin + per-key bias (needed by GEMM1 epilogue + attention)
    prep_kernel<<<(NHEADS * NSEQ + 127) / 128, 128>>>(lscale, lls);

    // 2) bf16x3 conversions for QKV GEMM
    convA_kernel<<<(M * 128 + 255) / 256, 256>>>(x, aexp, M);
    convB_kernel<<<(3 * DMODEL * DMODEL + 255) / 256, 256>>>(w_qkv, bexp, 3 * DMODEL);
    convB_kernel<<<(DMODEL * DMODEL + 255) / 256, 256>>>(w_o, bexp2, DMODEL);

    // 3) QKV projection; epilogue rotates and emits split-bf16 Q/K/Vh/Vl
    mmagemm<0><<<dim3(3 * DMODEL / 128, M / 128), 256, GEMM_SMEM>>>(aexp, bexp, nullptr, 3 * DMODEL);

    // 4) tensor-core flash attention; epilogue writes split A' for out-proj
    attn3_kernel<<<dim3(BATCH * NHEADS, NSEQ / 128), 256, ATT_SMEM>>>();

    // 5) output projection
    mmagemm<1><<<dim3(DMODEL / 128, M / 128), 256, GEMM_SMEM>>>(aexp, bexp2, out, DMODEL);
}

// round 11
// speedup vs baseline: 1.5511x; 1.3847x over previous
#include <cuda_runtime.h>
#include <cuda_bf16.h>
#include <cuda_fp16.h>
#include <cstdint>
#include <math.h>

#define BATCH   2
#define NSEQ    2048
#define DMODEL  512
#define NHEADS  8
#define DH      64
#define KP      32
#define KEXP    1536
#define TAU_F   6.283185307179586f

// ---------------- scratch (static device memory; no allocations) ----------------
__device__ __half g_qe[(size_t)BATCH * NHEADS * NSEQ * DH];          // fp16 rotated Q
__device__ __half g_ke[(size_t)BATCH * NHEADS * NSEQ * DH];          // fp16 rotated K
__device__ __half g_vh[(size_t)BATCH * NHEADS * NSEQ * DH];          // fp16 V
__device__ float g_cos[NHEADS * NSEQ * KP];
__device__ float g_sin[NHEADS * NSEQ * KP];
__device__ float g_bias[NHEADS * NSEQ];                              // lam*S_n/KP per head
__device__ __nv_bfloat16 g_aexp[(size_t)BATCH * NSEQ * KEXP];        // A' 4096x1536
__device__ __nv_bfloat16 g_bexp[(size_t)3 * DMODEL * KEXP];          // B' 1536x1536
__device__ __nv_bfloat16 g_bexp2[(size_t)DMODEL * KEXP];             // B2' 512x1536

__constant__ float c_zim[KP] = {
    14.134725142f, 21.022039639f, 25.01085758f,  30.424876126f,
    32.935061588f, 37.586178159f, 40.918719012f, 43.327073281f,
    48.005150881f, 49.773832478f, 52.970321478f, 56.446247697f,
    59.347044003f, 60.831778525f, 65.112544048f, 67.079810529f,
    69.546401711f, 72.067157674f, 75.704690699f, 77.144840069f,
    79.33737502f,  82.910380854f, 84.735492981f, 87.425274613f,
    88.809111208f, 92.491899271f, 94.651344041f, 95.870634228f,
    98.831194218f, 101.317851006f, 103.72553804f, 105.446623052f};

// ---------------- warp-MMA / async helpers (portable sm_80+ path) ----------------
__device__ __forceinline__ uint32_t smem_u32(const void* p) {
    uint32_t a;
    asm("{ .reg .u64 t; cvta.to.shared.u64 t, %1; cvt.u32.u64 %0, t; }" : "=r"(a) : "l"(p));
    return a;
}
__device__ __forceinline__ void ldsm4(uint32_t* r, uint32_t a) {
    asm volatile("ldmatrix.sync.aligned.m8n8.x4.shared.b16 {%0,%1,%2,%3}, [%4];"
                 : "=r"(r[0]), "=r"(r[1]), "=r"(r[2]), "=r"(r[3]) : "r"(a));
}
__device__ __forceinline__ void ldsm4t(uint32_t* r, uint32_t a) {
    asm volatile("ldmatrix.sync.aligned.m8n8.x4.trans.shared.b16 {%0,%1,%2,%3}, [%4];"
                 : "=r"(r[0]), "=r"(r[1]), "=r"(r[2]), "=r"(r[3]) : "r"(a));
}
__device__ __forceinline__ void mma16816(float* c, const uint32_t* a, uint32_t b0, uint32_t b1) {
    asm volatile("mma.sync.aligned.m16n8k16.row.col.f32.bf16.bf16.f32 "
                 "{%0,%1,%2,%3}, {%4,%5,%6,%7}, {%8,%9}, {%0,%1,%2,%3};"
                 : "+f"(c[0]), "+f"(c[1]), "+f"(c[2]), "+f"(c[3])
                 : "r"(a[0]), "r"(a[1]), "r"(a[2]), "r"(a[3]), "r"(b0), "r"(b1));
}
__device__ __forceinline__ void mma16816h(float* c, const uint32_t* a, uint32_t b0, uint32_t b1) {
    asm volatile("mma.sync.aligned.m16n8k16.row.col.f32.f16.f16.f32 "
                 "{%0,%1,%2,%3}, {%4,%5,%6,%7}, {%8,%9}, {%0,%1,%2,%3};"
                 : "+f"(c[0]), "+f"(c[1]), "+f"(c[2]), "+f"(c[3])
                 : "r"(a[0]), "r"(a[1]), "r"(a[2]), "r"(a[3]), "r"(b0), "r"(b1));
}
__device__ __forceinline__ void cpasync16(uint32_t dst, const void* src) {
    asm volatile("cp.async.cg.shared.global [%0], [%1], 16;" :: "r"(dst), "l"(src));
}
__device__ __forceinline__ void cpcommit() {
    asm volatile("cp.async.commit_group;");
}
template <int N>
__device__ __forceinline__ void cpwait() {
    asm volatile("cp.async.wait_group %0;" :: "n"(N));
}

// ---------------- bf16 mma GEMM: 8 warps x (64x32), fragment-pipelined ----------
// C[M,Ntot] = A'[M,1536] @ B'[Ntot,1536]^T, 128x128 CTA tile, K-tiles of 32.
#define KT (KEXP / 32)
#define SWZ(r, bc) ((uint32_t)((r) * 64 + ((bc) ^ ((((r) >> 1) & 3) << 4))))
#define GSTAGES 4
#define GSTG_SZ 16384               // A(8KB) + B(8KB) per stage
#define GEMM_SMEM (GSTAGES * GSTG_SZ)

template <int EPI>
__global__ __launch_bounds__(256, 2) void mmagemm(const __nv_bfloat16* __restrict__ A,
                                                  const __nv_bfloat16* __restrict__ Bm,
                                                  float* __restrict__ C, int Ntot) {
    extern __shared__ char gsm[];
    const uint32_t sbase = smem_u32(gsm);

    const int tid = threadIdx.x;
    const int lane = tid & 31;
    const int wid = tid >> 5;
    const int wm = (wid & 1) * 64;
    const int wn = (wid >> 1) * 32;
    const int row0 = blockIdx.y * 128;
    const int col0 = blockIdx.x * 128;

    const int lr = (lane & 7) + ((lane >> 3) & 1) * 8;
    const int kh = (lane >> 4) * 16;
    uint32_t aoff[4][2], boff[2][2];
#pragma unroll
    for (int mi = 0; mi < 4; mi++)
#pragma unroll
        for (int ks = 0; ks < 2; ks++) aoff[mi][ks] = SWZ(wm + mi * 16 + lr, ks * 32 + kh);
#pragma unroll
    for (int g = 0; g < 2; g++)
#pragma unroll
        for (int ks = 0; ks < 2; ks++) boff[g][ks] = SWZ(wn + g * 16 + lr, ks * 32 + kh);

    const int r_ld0 = tid >> 2, cu_ld = tid & 3;
    const int r_ld1 = r_ld0 + 64;
    const uint32_t so0 = SWZ(r_ld0, cu_ld * 16);
    const uint32_t so1 = SWZ(r_ld1, cu_ld * 16);
    const __nv_bfloat16* a0p = &A[(size_t)(row0 + r_ld0) * KEXP + cu_ld * 8];
    const __nv_bfloat16* a1p = &A[(size_t)(row0 + r_ld1) * KEXP + cu_ld * 8];
    const __nv_bfloat16* b0p = &Bm[(size_t)(col0 + r_ld0) * KEXP + cu_ld * 8];
    const __nv_bfloat16* b1p = &Bm[(size_t)(col0 + r_ld1) * KEXP + cu_ld * 8];

    auto load_tile = [&](int t) {
        const uint32_t st = sbase + (uint32_t)((t & (GSTAGES - 1)) * GSTG_SZ);
        const int k0 = t * 32;
        cpasync16(st + so0, a0p + k0);
        cpasync16(st + so1, a1p + k0);
        cpasync16(st + 8192 + so0, b0p + k0);
        cpasync16(st + 8192 + so1, b1p + k0);
        cpcommit();
    };
    load_tile(0);
    load_tile(1);
    load_tile(2);

    float acc[4][4][4];
#pragma unroll
    for (int mi = 0; mi < 4; mi++)
#pragma unroll
        for (int ni = 0; ni < 4; ni++)
#pragma unroll
            for (int q = 0; q < 4; q++) acc[mi][ni][q] = 0.0f;

    uint32_t af[2][4][4], bfr[2][2][4];

    cpwait<1>();
    __syncthreads();
    {
        const uint32_t bA = sbase;
#pragma unroll
        for (int mi = 0; mi < 4; mi++) ldsm4(af[0][mi], bA + aoff[mi][0]);
#pragma unroll
        for (int g = 0; g < 2; g++) ldsm4(bfr[0][g], bA + 8192 + boff[g][0]);
    }

    for (int t = 0; t < KT; t++) {
        const uint32_t bA = sbase + (uint32_t)((t & (GSTAGES - 1)) * GSTG_SZ);
        const int tn = (t + 1 < KT) ? t + 1 : t;
        const uint32_t bA1 = sbase + (uint32_t)((tn & (GSTAGES - 1)) * GSTG_SZ);

#pragma unroll
        for (int mi = 0; mi < 4; mi++) ldsm4(af[1][mi], bA + aoff[mi][1]);
#pragma unroll
        for (int g = 0; g < 2; g++) ldsm4(bfr[1][g], bA + 8192 + boff[g][1]);
#pragma unroll
        for (int mi = 0; mi < 4; mi++)
#pragma unroll
            for (int ni = 0; ni < 4; ni++)
                mma16816(acc[mi][ni], af[0][mi], bfr[0][ni >> 1][ni & 1], bfr[0][ni >> 1][(ni & 1) + 2]);

#pragma unroll
        for (int mi = 0; mi < 4; mi++) ldsm4(af[0][mi], bA1 + aoff[mi][0]);
#pragma unroll
        for (int g = 0; g < 2; g++) ldsm4(bfr[0][g], bA1 + 8192 + boff[g][0]);
#pragma unroll
        for (int mi = 0; mi < 4; mi++)
#pragma unroll
            for (int ni = 0; ni < 4; ni++)
                mma16816(acc[mi][ni], af[1][mi], bfr[1][ni >> 1][ni & 1], bfr[1][ni >> 1][(ni & 1) + 2]);

        if (t + 3 < KT) load_tile(t + 3);
        else cpcommit();
        cpwait<1>();
        __syncthreads();
    }

    // epilogue
#pragma unroll
    for (int mi = 0; mi < 4; mi++) {
#pragma unroll
        for (int ni = 0; ni < 4; ni++) {
            int m0 = row0 + wm + mi * 16 + (lane >> 2);
            int n = col0 + wn + ni * 8 + (lane & 3) * 2;
#pragma unroll
            for (int half = 0; half < 2; half++) {
                int m = m0 + half * 8;
                float v0 = acc[mi][ni][half * 2 + 0];
                float v1 = acc[mi][ni][half * 2 + 1];
                if (EPI == 1) {
                    *reinterpret_cast<float2*>(&C[(size_t)m * Ntot + n]) = make_float2(v0, v1);
                } else {
                    const int bb = m >> 11, nn = m & 2047;
                    const int sect = n >> 9;
                    const int h = (n >> 6) & 7;
                    const int d = n & 63;
                    size_t ob = ((size_t)((bb * NHEADS + h) * NSEQ) + nn) * DH + d;
                    if (sect == 2) {
                        *reinterpret_cast<__half2*>(&g_vh[ob]) =
                            __float22half2_rn(make_float2(v0, v1));
                    } else {
                        int ci = (h * NSEQ + nn) * KP + (d >> 1);
                        float c0 = g_cos[ci], s0 = g_sin[ci];
                        __half2 o2 = __float22half2_rn(
                            make_float2(v0 * c0 - v1 * s0, v0 * s0 + v1 * c0));
                        if (sect == 0) *reinterpret_cast<__half2*>(&g_qe[ob]) = o2;
                        else           *reinterpret_cast<__half2*>(&g_ke[ob]) = o2;
                    }
                }
            }
        }
    }
}

// ---------------- bf16x3 split conversions ----------------
__global__ void convA_kernel(const float* __restrict__ src, __nv_bfloat16* __restrict__ dst, int M) {
    int i = blockIdx.x * blockDim.x + threadIdx.x;
    if (i >= M * 128) return;
    int row = i >> 7, c4 = (i & 127) * 4;
    float4 v = *reinterpret_cast<const float4*>(&src[(size_t)row * DMODEL + c4]);
    __nv_bfloat16 h0 = __float2bfloat16(v.x), h1 = __float2bfloat16(v.y);
    __nv_bfloat16 h2 = __float2bfloat16(v.z), h3 = __float2bfloat16(v.w);
    __nv_bfloat16 l0 = __float2bfloat16(v.x - __bfloat162float(h0));
    __nv_bfloat16 l1 = __float2bfloat16(v.y - __bfloat162float(h1));
    __nv_bfloat16 l2 = __float2bfloat16(v.z - __bfloat162float(h2));
    __nv_bfloat16 l3 = __float2bfloat16(v.w - __bfloat162float(h3));
    size_t base = (size_t)row * KEXP + c4;
    __nv_bfloat162* d0 = reinterpret_cast<__nv_bfloat162*>(&dst[base]);
    __nv_bfloat162* d1 = reinterpret_cast<__nv_bfloat162*>(&dst[base + 512]);
    __nv_bfloat162* d2 = reinterpret_cast<__nv_bfloat162*>(&dst[base + 1024]);
    d0[0] = __nv_bfloat162(h0, h1); d0[1] = __nv_bfloat162(h2, h3);
    d1[0] = __nv_bfloat162(l0, l1); d1[1] = __nv_bfloat162(l2, l3);
    d2[0] = __nv_bfloat162(h0, h1); d2[1] = __nv_bfloat162(h2, h3);
}

__global__ void convB_kernel(const float* __restrict__ w, __nv_bfloat16* __restrict__ dst, int N) {
    int i = blockIdx.x * blockDim.x + threadIdx.x;
    if (i >= N * DMODEL) return;
    int k = i & 511, n = i >> 9;
    float v = w[(size_t)k * N + n];
    __nv_bfloat16 hi = __float2bfloat16(v);
    __nv_bfloat16 lo = __float2bfloat16(v - __bfloat162float(hi));
    size_t base = (size_t)n * KEXP + k;
    dst[base] = hi;
    dst[base + 512] = hi;
    dst[base + 1024] = lo;
}

// ---------------- theta / cos / sin / per-key bias ----------------
__global__ void prep_kernel(const float* __restrict__ log_scale,
                            const float* __restrict__ log_lambda_sigma) {
    int idx = blockIdx.x * blockDim.x + threadIdx.x;
    if (idx >= NHEADS * NSEQ) return;
    int h = idx / NSEQ;
    int n = idx % NSEQ;
    float sc = expf(log_scale[h]);
    float lam = expf(log_lambda_sigma[h]);
    float tau = log1pf((float)n);
    float ssum = 0.0f;
#pragma unroll
    for (int p = 0; p < KP; p++) {
        float g = c_zim[p] / c_zim[0];
        float th = tau * g * sc;
        g_cos[idx * KP + p] = cosf(th);
        g_sin[idx * KP + p] = sinf(th);
        ssum += floorf(th / TAU_F);
    }
    g_bias[idx] = lam * ssum * (1.0f / KP);
}

// ---------------- tensor-core flash attention, single fp16 MMA path ----------
// Q/K/V fp16 (64 cols, pitch 144B). QK: s = q*k (one MMA per fragment).
// PV: o += P*V (one MMA). fp16 eps ~2.4e-4 keeps rel_err well under 1e-3.
// Epilogue writes the bf16x3-split attention output straight into g_aexp.
#define VPITCH 144
#define QOFF   0
#define QSZ    (128 * VPITCH)                      // 18432
#define KSZ    (64 * VPITCH)                       // 9216
#define STSZ   (2 * KSZ + 256)                     // K + V + bias = 18688
#define KOFF(s)  (QSZ + (s) * STSZ)
#define VHOFF(s) (KOFF(s) + KSZ)
#define BOFF(s)  (VHOFF(s) + KSZ)
#define ATT_SMEM (QSZ + 2 * STSZ)                  // 55808

__global__ __launch_bounds__(256, 2) void attn3_kernel() {
    extern __shared__ char smc[];
    const uint32_t smb = smem_u32(smc);
    const int tid = threadIdx.x;
    const int lane = tid & 31;
    const int wid = tid >> 5;
    const int bh = blockIdx.x;
    const int h = bh & (NHEADS - 1);
    const int b = bh >> 3;
    const int qbase = (15 - (int)blockIdx.y) << 7;
    const int ntiles = (qbase >> 6) + 2;

    const __half* qe = g_qe + (size_t)bh * NSEQ * DH;
    const __half* ke = g_ke + (size_t)bh * NSEQ * DH;
    const __half* vh = g_vh + (size_t)bh * NSEQ * DH;
    const float* bp = g_bias + h * NSEQ;

    // Q tile: 128 rows x 128B
    for (int i = tid; i < 1024; i += 256) {
        int r = i >> 3, c = i & 7;
        cpasync16(smb + QOFF + r * VPITCH + c * 16, qe + (size_t)(qbase + r) * DH + c * 8);
    }
    auto load_tile = [&](int t, int st) {
        int jg = t << 6;
#pragma unroll
        for (int q = 0; q < 2; q++) {           // K, V: 64 rows x 128B each
            int i = q * 256 + tid, r = i >> 3, c = i & 7;
            cpasync16(smb + KOFF(st) + r * VPITCH + c * 16, ke + (size_t)(jg + r) * DH + c * 8);
            cpasync16(smb + VHOFF(st) + r * VPITCH + c * 16, vh + (size_t)(jg + r) * DH + c * 8);
        }
        if (tid < 16) cpasync16(smb + BOFF(st) + tid * 16, bp + jg + tid * 4);
    };
    load_tile(0, 0);
    cpcommit();
    load_tile(1, 1);
    cpcommit();

    const uint32_t qaddr = smb + QOFF + (wid * 16 + (lane & 15)) * VPITCH + (lane >> 4) * 16;
    const uint32_t klocal = (uint32_t)((lane & 15) * VPITCH + (lane >> 4) * 16);

    float o[8][4];
#pragma unroll
    for (int i = 0; i < 8; i++)
#pragma unroll
        for (int q = 0; q < 4; q++) o[i][q] = 0.0f;
    float m0 = -INFINITY, m1 = -INFINITY, l0 = 0.0f, l1 = 0.0f;
    const int qm0 = qbase + wid * 16 + (lane >> 2);
    const int qm1 = qm0 + 8;

    for (int t = 0; t < ntiles; t++) {
        if (t < ntiles - 1) cpwait<1>(); else cpwait<0>();
        __syncthreads();
        const int st = t & 1;
        const int jg = t << 6;

        // ---- S = Q K^T (fp16) ----
        float s[8][4];
#pragma unroll
        for (int i = 0; i < 8; i++)
#pragma unroll
            for (int q = 0; q < 4; q++) s[i][q] = 0.0f;
        const uint32_t kb = smb + KOFF(st);
#pragma unroll
        for (int ks = 0; ks < 4; ks++) {
            uint32_t a[4];
            ldsm4(a, qaddr + ks * 32);
#pragma unroll
            for (int ng = 0; ng < 4; ng++) {
                uint32_t bfr[4];
                ldsm4(bfr, kb + klocal + ng * (16 * VPITCH) + ks * 32);
                mma16816h(s[2 * ng],     a, bfr[0], bfr[2]);
                mma16816h(s[2 * ng + 1], a, bfr[1], bfr[3]);
            }
        }

        const bool masked = (t >= ntiles - 2);
#pragma unroll
        for (int nf = 0; nf < 8; nf++) {
            int col = jg + nf * 8 + ((lane & 3) << 1);
            float2 bj = *reinterpret_cast<const float2*>(smc + BOFF(st) + (nf * 8 + ((lane & 3) << 1)) * 4);
            s[nf][0] = s[nf][0] * 0.125f + bj.x;
            s[nf][1] = s[nf][1] * 0.125f + bj.y;
            s[nf][2] = s[nf][2] * 0.125f + bj.x;
            s[nf][3] = s[nf][3] * 0.125f + bj.y;
            if (masked) {
                if (col > qm0)     s[nf][0] = -INFINITY;
                if (col + 1 > qm0) s[nf][1] = -INFINITY;
                if (col > qm1)     s[nf][2] = -INFINITY;
                if (col + 1 > qm1) s[nf][3] = -INFINITY;
            }
        }

        float mx0 = -INFINITY, mx1 = -INFINITY;
#pragma unroll
        for (int nf = 0; nf < 8; nf++) {
            mx0 = fmaxf(mx0, fmaxf(s[nf][0], s[nf][1]));
            mx1 = fmaxf(mx1, fmaxf(s[nf][2], s[nf][3]));
        }
        mx0 = fmaxf(mx0, __shfl_xor_sync(0xffffffffu, mx0, 1));
        mx0 = fmaxf(mx0, __shfl_xor_sync(0xffffffffu, mx0, 2));
        mx1 = fmaxf(mx1, __shfl_xor_sync(0xffffffffu, mx1, 1));
        mx1 = fmaxf(mx1, __shfl_xor_sync(0xffffffffu, mx1, 2));
        float mn0 = fmaxf(m0, mx0), mn1 = fmaxf(m1, mx1);
        float corr0 = __expf(m0 - mn0), corr1 = __expf(m1 - mn1);
        m0 = mn0; m1 = mn1;
        float ps0 = 0.0f, ps1 = 0.0f;
#pragma unroll
        for (int nf = 0; nf < 8; nf++) {
            s[nf][0] = __expf(s[nf][0] - mn0);
            s[nf][1] = __expf(s[nf][1] - mn0);
            s[nf][2] = __expf(s[nf][2] - mn1);
            s[nf][3] = __expf(s[nf][3] - mn1);
            ps0 += s[nf][0] + s[nf][1];
            ps1 += s[nf][2] + s[nf][3];
        }
        ps0 += __shfl_xor_sync(0xffffffffu, ps0, 1);
        ps0 += __shfl_xor_sync(0xffffffffu, ps0, 2);
        ps1 += __shfl_xor_sync(0xffffffffu, ps1, 1);
        ps1 += __shfl_xor_sync(0xffffffffu, ps1, 2);
        l0 = l0 * corr0 + ps0;
        l1 = l1 * corr1 + ps1;
#pragma unroll
        for (int nf = 0; nf < 8; nf++) {
            o[nf][0] *= corr0; o[nf][1] *= corr0;
            o[nf][2] *= corr1; o[nf][3] *= corr1;
        }

        // ---- O += P V (fp16) ----
        const uint32_t vhb = smb + VHOFF(st);
#pragma unroll
        for (int ks2 = 0; ks2 < 4; ks2++) {
            const int f0 = 2 * ks2, f1 = 2 * ks2 + 1;
            __half2 p0 = __float22half2_rn(make_float2(s[f0][0], s[f0][1]));
            __half2 p1 = __float22half2_rn(make_float2(s[f0][2], s[f0][3]));
            __half2 p2 = __float22half2_rn(make_float2(s[f1][0], s[f1][1]));
            __half2 p3 = __float22half2_rn(make_float2(s[f1][2], s[f1][3]));
            uint32_t ah[4] = {*(uint32_t*)&p0, *(uint32_t*)&p1, *(uint32_t*)&p2, *(uint32_t*)&p3};
#pragma unroll
            for (int dseg = 0; dseg < 4; dseg++) {
                uint32_t bhf[4];
                ldsm4t(bhf, vhb + ks2 * (16 * VPITCH) + klocal + dseg * 32);
                mma16816h(o[2 * dseg],     ah, bhf[0], bhf[1]);
                mma16816h(o[2 * dseg + 1], ah, bhf[2], bhf[3]);
            }
        }

        __syncthreads();
        if (t + 2 < ntiles) { load_tile(t + 2, st); cpcommit(); }
    }

    // ---- normalize + write bf16x3 split directly into g_aexp ([hi|lo|hi]) ----
    const float inv0 = 1.0f / l0, inv1 = 1.0f / l1;
#pragma unroll
    for (int nf = 0; nf < 8; nf++) {
        int col = h * DH + nf * 8 + ((lane & 3) << 1);
        size_t r0 = (size_t)(b * NSEQ + qm0) * KEXP + col;
        size_t r1 = (size_t)(b * NSEQ + qm1) * KEXP + col;
        float x0 = o[nf][0] * inv0, y0 = o[nf][1] * inv0;
        float x1 = o[nf][2] * inv1, y1 = o[nf][3] * inv1;
        __nv_bfloat162 h0 = __float22bfloat162_rn(make_float2(x0, y0));
        __nv_bfloat162 l0b = __float22bfloat162_rn(
            make_float2(x0 - __low2float(h0), y0 - __high2float(h0)));
        __nv_bfloat162 h1 = __float22bfloat162_rn(make_float2(x1, y1));
        __nv_bfloat162 l1b = __float22bfloat162_rn(
            make_float2(x1 - __low2float(h1), y1 - __high2float(h1)));
        *reinterpret_cast<__nv_bfloat162*>(&g_aexp[r0]) = h0;
        *reinterpret_cast<__nv_bfloat162*>(&g_aexp[r0 + 512]) = l0b;
        *reinterpret_cast<__nv_bfloat162*>(&g_aexp[r0 + 1024]) = h0;
        *reinterpret_cast<__nv_bfloat162*>(&g_aexp[r1]) = h1;
        *reinterpret_cast<__nv_bfloat162*>(&g_aexp[r1 + 512]) = l1b;
        *reinterpret_cast<__nv_bfloat162*>(&g_aexp[r1 + 1024]) = h1;
    }
}

// ---------------- launch ----------------
extern "C" void kernel_launch(void* const* d_in, const int* in_sizes, int n_in,
                              void* d_out, int out_size) {
    const float* x      = (const float*)d_in[0];
    const float* w_qkv  = (const float*)d_in[1];
    const float* w_o    = (const float*)d_in[2];
    const float* lscale = (const float*)d_in[3];
    const float* lls    = (const float*)d_in[4];
    float* out = (float*)d_out;

    __nv_bfloat16 *aexp, *bexp, *bexp2;
    cudaGetSymbolAddress((void**)&aexp, g_aexp);
    cudaGetSymbolAddress((void**)&bexp, g_bexp);
    cudaGetSymbolAddress((void**)&bexp2, g_bexp2);

    const int M = BATCH * NSEQ;   // 4096
    cudaFuncSetAttribute(attn3_kernel, cudaFuncAttributeMaxDynamicSharedMemorySize, ATT_SMEM);
    cudaFuncSetAttribute(mmagemm<0>, cudaFuncAttributeMaxDynamicSharedMemorySize, GEMM_SMEM);
    cudaFuncSetAttribute(mmagemm<1>, cudaFuncAttributeMaxDynamicSharedMemorySize, GEMM_SMEM);

    // 1) theta/cos/sin + per-key bias (needed by GEMM1 epilogue + attention)
    prep_kernel<<<(NHEADS * NSEQ + 127) / 128, 128>>>(lscale, lls);

    // 2) bf16x3 conversions for QKV GEMM + out-proj weights
    convA_kernel<<<(M * 128 + 255) / 256, 256>>>(x, aexp, M);
    convB_kernel<<<(3 * DMODEL * DMODEL + 255) / 256, 256>>>(w_qkv, bexp, 3 * DMODEL);
    convB_kernel<<<(DMODEL * DMODEL + 255) / 256, 256>>>(w_o, bexp2, DMODEL);

    // 3) QKV projection; epilogue rotates and emits fp16 Q/K/V
    mmagemm<0><<<dim3(3 * DMODEL / 128, M / 128), 256, GEMM_SMEM>>>(aexp, bexp, nullptr, 3 * DMODEL);

    // 4) fp16 tensor-core flash attention; epilogue writes split A' for out-proj
    attn3_kernel<<<dim3(BATCH * NHEADS, NSEQ / 128), 256, ATT_SMEM>>>();

    // 5) output projection
    mmagemm<1><<<dim3(DMODEL / 128, M / 128), 256, GEMM_SMEM>>>(aexp, bexp2, out, DMODEL);
}

// round 12
// speedup vs baseline: 1.8874x; 1.2168x over previous
#include <cuda_runtime.h>
#include <cuda_bf16.h>
#include <cuda_fp16.h>
#include <cstdint>
#include <math.h>

#define BATCH   2
#define NSEQ    2048
#define DMODEL  512
#define NHEADS  8
#define DH      64
#define KP      32
#define KEXP    1024
#define TAU_F   6.283185307179586f

// ---------------- scratch (static device memory; no allocations) ----------------
__device__ __half g_qe[(size_t)BATCH * NHEADS * NSEQ * DH];          // fp16 rotated Q
__device__ __half g_ke[(size_t)BATCH * NHEADS * NSEQ * DH];          // fp16 rotated K
__device__ __half g_vh[(size_t)BATCH * NHEADS * NSEQ * DH];          // fp16 V
__device__ float g_cos[NHEADS * NSEQ * KP];
__device__ float g_sin[NHEADS * NSEQ * KP];
__device__ float g_bias[NHEADS * NSEQ];                              // lam*S_n/KP per head
__device__ __half g_aexp[(size_t)BATCH * NSEQ * KEXP];               // A' = [Ah|Al]
__device__ __half g_bexp[(size_t)3 * DMODEL * KEXP];                 // B' = [Bh|Bh] (w_qkv)
__device__ __half g_bexp2[(size_t)DMODEL * KEXP];                    // B2' = [Bh|Bh] (w_o)

__constant__ float c_zim[KP] = {
    14.134725142f, 21.022039639f, 25.01085758f,  30.424876126f,
    32.935061588f, 37.586178159f, 40.918719012f, 43.327073281f,
    48.005150881f, 49.773832478f, 52.970321478f, 56.446247697f,
    59.347044003f, 60.831778525f, 65.112544048f, 67.079810529f,
    69.546401711f, 72.067157674f, 75.704690699f, 77.144840069f,
    79.33737502f,  82.910380854f, 84.735492981f, 87.425274613f,
    88.809111208f, 92.491899271f, 94.651344041f, 95.870634228f,
    98.831194218f, 101.317851006f, 103.72553804f, 105.446623052f};

// ---------------- warp-MMA / async helpers (portable sm_80+ path) ----------------
__device__ __forceinline__ uint32_t smem_u32(const void* p) {
    uint32_t a;
    asm("{ .reg .u64 t; cvta.to.shared.u64 t, %1; cvt.u32.u64 %0, t; }" : "=r"(a) : "l"(p));
    return a;
}
__device__ __forceinline__ void ldsm4(uint32_t* r, uint32_t a) {
    asm volatile("ldmatrix.sync.aligned.m8n8.x4.shared.b16 {%0,%1,%2,%3}, [%4];"
                 : "=r"(r[0]), "=r"(r[1]), "=r"(r[2]), "=r"(r[3]) : "r"(a));
}
__device__ __forceinline__ void ldsm4t(uint32_t* r, uint32_t a) {
    asm volatile("ldmatrix.sync.aligned.m8n8.x4.trans.shared.b16 {%0,%1,%2,%3}, [%4];"
                 : "=r"(r[0]), "=r"(r[1]), "=r"(r[2]), "=r"(r[3]) : "r"(a));
}
__device__ __forceinline__ void mma16816h(float* c, const uint32_t* a, uint32_t b0, uint32_t b1) {
    asm volatile("mma.sync.aligned.m16n8k16.row.col.f32.f16.f16.f32 "
                 "{%0,%1,%2,%3}, {%4,%5,%6,%7}, {%8,%9}, {%0,%1,%2,%3};"
                 : "+f"(c[0]), "+f"(c[1]), "+f"(c[2]), "+f"(c[3])
                 : "r"(a[0]), "r"(a[1]), "r"(a[2]), "r"(a[3]), "r"(b0), "r"(b1));
}
__device__ __forceinline__ void cpasync16(uint32_t dst, const void* src) {
    asm volatile("cp.async.cg.shared.global [%0], [%1], 16;" :: "r"(dst), "l"(src));
}
__device__ __forceinline__ void cpcommit() {
    asm volatile("cp.async.commit_group;");
}
template <int N>
__device__ __forceinline__ void cpwait() {
    asm volatile("cp.async.wait_group %0;" :: "n"(N));
}

// ---------------- fp16x2 mma GEMM: 8 warps x (64x32), fragment-pipelined ----------
// C[M,Ntot] = A'[M,1024] @ B'[Ntot,1024]^T  ( = A @ Bh exactly, fp16x2 split)
#define KT (KEXP / 32)
#define SWZ(r, bc) ((uint32_t)((r) * 64 + ((bc) ^ ((((r) >> 1) & 3) << 4))))
#define GSTAGES 4
#define GSTG_SZ 16384               // A(8KB) + B(8KB) per stage
#define GEMM_SMEM (GSTAGES * GSTG_SZ)

template <int EPI>
__global__ __launch_bounds__(256, 2) void mmagemm(const __half* __restrict__ A,
                                                  const __half* __restrict__ Bm,
                                                  float* __restrict__ C, int Ntot) {
    extern __shared__ char gsm[];
    const uint32_t sbase = smem_u32(gsm);

    const int tid = threadIdx.x;
    const int lane = tid & 31;
    const int wid = tid >> 5;
    const int wm = (wid & 1) * 64;
    const int wn = (wid >> 1) * 32;
    const int row0 = blockIdx.y * 128;
    const int col0 = blockIdx.x * 128;

    const int lr = (lane & 7) + ((lane >> 3) & 1) * 8;
    const int kh = (lane >> 4) * 16;
    uint32_t aoff[4][2], boff[2][2];
#pragma unroll
    for (int mi = 0; mi < 4; mi++)
#pragma unroll
        for (int ks = 0; ks < 2; ks++) aoff[mi][ks] = SWZ(wm + mi * 16 + lr, ks * 32 + kh);
#pragma unroll
    for (int g = 0; g < 2; g++)
#pragma unroll
        for (int ks = 0; ks < 2; ks++) boff[g][ks] = SWZ(wn + g * 16 + lr, ks * 32 + kh);

    const int r_ld0 = tid >> 2, cu_ld = tid & 3;
    const int r_ld1 = r_ld0 + 64;
    const uint32_t so0 = SWZ(r_ld0, cu_ld * 16);
    const uint32_t so1 = SWZ(r_ld1, cu_ld * 16);
    const __half* a0p = &A[(size_t)(row0 + r_ld0) * KEXP + cu_ld * 8];
    const __half* a1p = &A[(size_t)(row0 + r_ld1) * KEXP + cu_ld * 8];
    const __half* b0p = &Bm[(size_t)(col0 + r_ld0) * KEXP + cu_ld * 8];
    const __half* b1p = &Bm[(size_t)(col0 + r_ld1) * KEXP + cu_ld * 8];

    auto load_tile = [&](int t) {
        const uint32_t st = sbase + (uint32_t)((t & (GSTAGES - 1)) * GSTG_SZ);
        const int k0 = t * 32;
        cpasync16(st + so0, a0p + k0);
        cpasync16(st + so1, a1p + k0);
        cpasync16(st + 8192 + so0, b0p + k0);
        cpasync16(st + 8192 + so1, b1p + k0);
        cpcommit();
    };
    load_tile(0);
    load_tile(1);
    load_tile(2);

    float acc[4][4][4];
#pragma unroll
    for (int mi = 0; mi < 4; mi++)
#pragma unroll
        for (int ni = 0; ni < 4; ni++)
#pragma unroll
            for (int q = 0; q < 4; q++) acc[mi][ni][q] = 0.0f;

    uint32_t af[2][4][4], bfr[2][2][4];

    cpwait<1>();
    __syncthreads();
    {
        const uint32_t bA = sbase;
#pragma unroll
        for (int mi = 0; mi < 4; mi++) ldsm4(af[0][mi], bA + aoff[mi][0]);
#pragma unroll
        for (int g = 0; g < 2; g++) ldsm4(bfr[0][g], bA + 8192 + boff[g][0]);
    }

    for (int t = 0; t < KT; t++) {
        const uint32_t bA = sbase + (uint32_t)((t & (GSTAGES - 1)) * GSTG_SZ);
        const int tn = (t + 1 < KT) ? t + 1 : t;
        const uint32_t bA1 = sbase + (uint32_t)((tn & (GSTAGES - 1)) * GSTG_SZ);

#pragma unroll
        for (int mi = 0; mi < 4; mi++) ldsm4(af[1][mi], bA + aoff[mi][1]);
#pragma unroll
        for (int g = 0; g < 2; g++) ldsm4(bfr[1][g], bA + 8192 + boff[g][1]);
#pragma unroll
        for (int mi = 0; mi < 4; mi++)
#pragma unroll
            for (int ni = 0; ni < 4; ni++)
                mma16816h(acc[mi][ni], af[0][mi], bfr[0][ni >> 1][ni & 1], bfr[0][ni >> 1][(ni & 1) + 2]);

#pragma unroll
        for (int mi = 0; mi < 4; mi++) ldsm4(af[0][mi], bA1 + aoff[mi][0]);
#pragma unroll
        for (int g = 0; g < 2; g++) ldsm4(bfr[0][g], bA1 + 8192 + boff[g][0]);
#pragma unroll
        for (int mi = 0; mi < 4; mi++)
#pragma unroll
            for (int ni = 0; ni < 4; ni++)
                mma16816h(acc[mi][ni], af[1][mi], bfr[1][ni >> 1][ni & 1], bfr[1][ni >> 1][(ni & 1) + 2]);

        if (t + 3 < KT) load_tile(t + 3);
        else cpcommit();
        cpwait<1>();
        __syncthreads();
    }

    // epilogue
#pragma unroll
    for (int mi = 0; mi < 4; mi++) {
#pragma unroll
        for (int ni = 0; ni < 4; ni++) {
            int m0 = row0 + wm + mi * 16 + (lane >> 2);
            int n = col0 + wn + ni * 8 + (lane & 3) * 2;
#pragma unroll
            for (int half = 0; half < 2; half++) {
                int m = m0 + half * 8;
                float v0 = acc[mi][ni][half * 2 + 0];
                float v1 = acc[mi][ni][half * 2 + 1];
                if (EPI == 1) {
                    *reinterpret_cast<float2*>(&C[(size_t)m * Ntot + n]) = make_float2(v0, v1);
                } else {
                    const int bb = m >> 11, nn = m & 2047;
                    const int sect = n >> 9;
                    const int h = (n >> 6) & 7;
                    const int d = n & 63;
                    size_t ob = ((size_t)((bb * NHEADS + h) * NSEQ) + nn) * DH + d;
                    if (sect == 2) {
                        *reinterpret_cast<__half2*>(&g_vh[ob]) =
                            __float22half2_rn(make_float2(v0, v1));
                    } else {
                        int ci = (h * NSEQ + nn) * KP + (d >> 1);
                        float c0 = g_cos[ci], s0 = g_sin[ci];
                        __half2 o2 = __float22half2_rn(
                            make_float2(v0 * c0 - v1 * s0, v0 * s0 + v1 * c0));
                        if (sect == 0) *reinterpret_cast<__half2*>(&g_qe[ob]) = o2;
                        else           *reinterpret_cast<__half2*>(&g_ke[ob]) = o2;
                    }
                }
            }
        }
    }
}

// ---------------- fp16x2 split conversions ----------------
// A' = [Ah | Al] along K (exact representation of A)
__global__ void convA_kernel(const float* __restrict__ src, __half* __restrict__ dst, int M) {
    int i = blockIdx.x * blockDim.x + threadIdx.x;
    if (i >= M * 128) return;
    int row = i >> 7, c4 = (i & 127) * 4;
    float4 v = *reinterpret_cast<const float4*>(&src[(size_t)row * DMODEL + c4]);
    __half h0 = __float2half(v.x), h1 = __float2half(v.y);
    __half h2 = __float2half(v.z), h3 = __float2half(v.w);
    __half l0 = __float2half(v.x - __half2float(h0));
    __half l1 = __float2half(v.y - __half2float(h1));
    __half l2 = __float2half(v.z - __half2float(h2));
    __half l3 = __float2half(v.w - __half2float(h3));
    size_t base = (size_t)row * KEXP + c4;
    __half2* d0 = reinterpret_cast<__half2*>(&dst[base]);
    __half2* d1 = reinterpret_cast<__half2*>(&dst[base + 512]);
    d0[0] = __half2(h0, h1); d0[1] = __half2(h2, h3);
    d1[0] = __half2(l0, l1); d1[1] = __half2(l2, l3);
}

// B' = [Bh | Bh] along K; src w is (512, N) row-major; dst (N, 1024)
__global__ void convB_kernel(const float* __restrict__ w, __half* __restrict__ dst, int N) {
    int i = blockIdx.x * blockDim.x + threadIdx.x;
    if (i >= N * DMODEL) return;
    int k = i & 511, n = i >> 9;
    __half hi = __float2half(w[(size_t)k * N + n]);
    size_t base = (size_t)n * KEXP + k;
    dst[base] = hi;
    dst[base + 512] = hi;
}

// ---------------- theta / cos / sin / per-key bias ----------------
__global__ void prep_kernel(const float* __restrict__ log_scale,
                            const float* __restrict__ log_lambda_sigma) {
    int idx = blockIdx.x * blockDim.x + threadIdx.x;
    if (idx >= NHEADS * NSEQ) return;
    int h = idx / NSEQ;
    int n = idx % NSEQ;
    float sc = expf(log_scale[h]);
    float lam = expf(log_lambda_sigma[h]);
    float tau = log1pf((float)n);
    float ssum = 0.0f;
#pragma unroll
    for (int p = 0; p < KP; p++) {
        float g = c_zim[p] / c_zim[0];
        float th = tau * g * sc;
        g_cos[idx * KP + p] = cosf(th);
        g_sin[idx * KP + p] = sinf(th);
        ssum += floorf(th / TAU_F);
    }
    g_bias[idx] = lam * ssum * (1.0f / KP);
}

// ---------------- tensor-core flash attention, single fp16 MMA path ----------
// Q/K/V fp16 (64 cols, pitch 144B). Epilogue writes fp16x2 [Oh|Ol] into g_aexp.
#define VPITCH 144
#define QOFF   0
#define QSZ    (128 * VPITCH)                      // 18432
#define KSZ    (64 * VPITCH)                       // 9216
#define STSZ   (2 * KSZ + 256)                     // K + V + bias = 18688
#define KOFF(s)  (QSZ + (s) * STSZ)
#define VHOFF(s) (KOFF(s) + KSZ)
#define BOFF(s)  (VHOFF(s) + KSZ)
#define ATT_SMEM (QSZ + 2 * STSZ)                  // 55808

__global__ __launch_bounds__(256, 2) void attn3_kernel() {
    extern __shared__ char smc[];
    const uint32_t smb = smem_u32(smc);
    const int tid = threadIdx.x;
    const int lane = tid & 31;
    const int wid = tid >> 5;
    const int bh = blockIdx.x;
    const int h = bh & (NHEADS - 1);
    const int b = bh >> 3;
    const int qbase = (15 - (int)blockIdx.y) << 7;
    const int ntiles = (qbase >> 6) + 2;

    const __half* qe = g_qe + (size_t)bh * NSEQ * DH;
    const __half* ke = g_ke + (size_t)bh * NSEQ * DH;
    const __half* vh = g_vh + (size_t)bh * NSEQ * DH;
    const float* bp = g_bias + h * NSEQ;

    for (int i = tid; i < 1024; i += 256) {
        int r = i >> 3, c = i & 7;
        cpasync16(smb + QOFF + r * VPITCH + c * 16, qe + (size_t)(qbase + r) * DH + c * 8);
    }
    auto load_tile = [&](int t, int st) {
        int jg = t << 6;
#pragma unroll
        for (int q = 0; q < 2; q++) {
            int i = q * 256 + tid, r = i >> 3, c = i & 7;
            cpasync16(smb + KOFF(st) + r * VPITCH + c * 16, ke + (size_t)(jg + r) * DH + c * 8);
            cpasync16(smb + VHOFF(st) + r * VPITCH + c * 16, vh + (size_t)(jg + r) * DH + c * 8);
        }
        if (tid < 16) cpasync16(smb + BOFF(st) + tid * 16, bp + jg + tid * 4);
    };
    load_tile(0, 0);
    cpcommit();
    load_tile(1, 1);
    cpcommit();

    const uint32_t qaddr = smb + QOFF + (wid * 16 + (lane & 15)) * VPITCH + (lane >> 4) * 16;
    const uint32_t klocal = (uint32_t)((lane & 15) * VPITCH + (lane >> 4) * 16);

    float o[8][4];
#pragma unroll
    for (int i = 0; i < 8; i++)
#pragma unroll
        for (int q = 0; q < 4; q++) o[i][q] = 0.0f;
    float m0 = -INFINITY, m1 = -INFINITY, l0 = 0.0f, l1 = 0.0f;
    const int qm0 = qbase + wid * 16 + (lane >> 2);
    const int qm1 = qm0 + 8;

    for (int t = 0; t < ntiles; t++) {
        if (t < ntiles - 1) cpwait<1>(); else cpwait<0>();
        __syncthreads();
        const int st = t & 1;
        const int jg = t << 6;

        float s[8][4];
#pragma unroll
        for (int i = 0; i < 8; i++)
#pragma unroll
            for (int q = 0; q < 4; q++) s[i][q] = 0.0f;
        const uint32_t kb = smb + KOFF(st);
#pragma unroll
        for (int ks = 0; ks < 4; ks++) {
            uint32_t a[4];
            ldsm4(a, qaddr + ks * 32);
#pragma unroll
            for (int ng = 0; ng < 4; ng++) {
                uint32_t bfr[4];
                ldsm4(bfr, kb + klocal + ng * (16 * VPITCH) + ks * 32);
                mma16816h(s[2 * ng],     a, bfr[0], bfr[2]);
                mma16816h(s[2 * ng + 1], a, bfr[1], bfr[3]);
            }
        }

        const bool masked = (t >= ntiles - 2);
#pragma unroll
        for (int nf = 0; nf < 8; nf++) {
            int col = jg + nf * 8 + ((lane & 3) << 1);
            float2 bj = *reinterpret_cast<const float2*>(smc + BOFF(st) + (nf * 8 + ((lane & 3) << 1)) * 4);
            s[nf][0] = s[nf][0] * 0.125f + bj.x;
            s[nf][1] = s[nf][1] * 0.125f + bj.y;
            s[nf][2] = s[nf][2] * 0.125f + bj.x;
            s[nf][3] = s[nf][3] * 0.125f + bj.y;
            if (masked) {
                if (col > qm0)     s[nf][0] = -INFINITY;
                if (col + 1 > qm0) s[nf][1] = -INFINITY;
                if (col > qm1)     s[nf][2] = -INFINITY;
                if (col + 1 > qm1) s[nf][3] = -INFINITY;
            }
        }

        float mx0 = -INFINITY, mx1 = -INFINITY;
#pragma unroll
        for (int nf = 0; nf < 8; nf++) {
            mx0 = fmaxf(mx0, fmaxf(s[nf][0], s[nf][1]));
            mx1 = fmaxf(mx1, fmaxf(s[nf][2], s[nf][3]));
        }
        mx0 = fmaxf(mx0, __shfl_xor_sync(0xffffffffu, mx0, 1));
        mx0 = fmaxf(mx0, __shfl_xor_sync(0xffffffffu, mx0, 2));
        mx1 = fmaxf(mx1, __shfl_xor_sync(0xffffffffu, mx1, 1));
        mx1 = fmaxf(mx1, __shfl_xor_sync(0xffffffffu, mx1, 2));
        float mn0 = fmaxf(m0, mx0), mn1 = fmaxf(m1, mx1);
        float corr0 = __expf(m0 - mn0), corr1 = __expf(m1 - mn1);
        m0 = mn0; m1 = mn1;
        float ps0 = 0.0f, ps1 = 0.0f;
#pragma unroll
        for (int nf = 0; nf < 8; nf++) {
            s[nf][0] = __expf(s[nf][0] - mn0);
            s[nf][1] = __expf(s[nf][1] - mn0);
            s[nf][2] = __expf(s[nf][2] - mn1);
            s[nf][3] = __expf(s[nf][3] - mn1);
            ps0 += s[nf][0] + s[nf][1];
            ps1 += s[nf][2] + s[nf][3];
        }
        ps0 += __shfl_xor_sync(0xffffffffu, ps0, 1);
        ps0 += __shfl_xor_sync(0xffffffffu, ps0, 2);
        ps1 += __shfl_xor_sync(0xffffffffu, ps1, 1);
        ps1 += __shfl_xor_sync(0xffffffffu, ps1, 2);
        l0 = l0 * corr0 + ps0;
        l1 = l1 * corr1 + ps1;
#pragma unroll
        for (int nf = 0; nf < 8; nf++) {
            o[nf][0] *= corr0; o[nf][1] *= corr0;
            o[nf][2] *= corr1; o[nf][3] *= corr1;
        }

        const uint32_t vhb = smb + VHOFF(st);
#pragma unroll
        for (int ks2 = 0; ks2 < 4; ks2++) {
            const int f0 = 2 * ks2, f1 = 2 * ks2 + 1;
            __half2 p0 = __float22half2_rn(make_float2(s[f0][0], s[f0][1]));
            __half2 p1 = __float22half2_rn(make_float2(s[f0][2], s[f0][3]));
            __half2 p2 = __float22half2_rn(make_float2(s[f1][0], s[f1][1]));
            __half2 p3 = __float22half2_rn(make_float2(s[f1][2], s[f1][3]));
            uint32_t ah[4] = {*(uint32_t*)&p0, *(uint32_t*)&p1, *(uint32_t*)&p2, *(uint32_t*)&p3};
#pragma unroll
            for (int dseg = 0; dseg < 4; dseg++) {
                uint32_t bhf[4];
                ldsm4t(bhf, vhb + ks2 * (16 * VPITCH) + klocal + dseg * 32);
                mma16816h(o[2 * dseg],     ah, bhf[0], bhf[1]);
                mma16816h(o[2 * dseg + 1], ah, bhf[2], bhf[3]);
            }
        }

        __syncthreads();
        if (t + 2 < ntiles) { load_tile(t + 2, st); cpcommit(); }
    }

    // ---- normalize + write fp16x2 split [Oh|Ol] directly into g_aexp ----
    const float inv0 = 1.0f / l0, inv1 = 1.0f / l1;
#pragma unroll
    for (int nf = 0; nf < 8; nf++) {
        int col = h * DH + nf * 8 + ((lane & 3) << 1);
        size_t r0 = (size_t)(b * NSEQ + qm0) * KEXP + col;
        size_t r1 = (size_t)(b * NSEQ + qm1) * KEXP + col;
        float x0 = o[nf][0] * inv0, y0 = o[nf][1] * inv0;
        float x1 = o[nf][2] * inv1, y1 = o[nf][3] * inv1;
        __half2 h0 = __float22half2_rn(make_float2(x0, y0));
        __half2 l0h = __float22half2_rn(
            make_float2(x0 - __low2float(h0), y0 - __high2float(h0)));
        __half2 h1 = __float22half2_rn(make_float2(x1, y1));
        __half2 l1h = __float22half2_rn(
            make_float2(x1 - __low2float(h1), y1 - __high2float(h1)));
        *reinterpret_cast<__half2*>(&g_aexp[r0]) = h0;
        *reinterpret_cast<__half2*>(&g_aexp[r0 + 512]) = l0h;
        *reinterpret_cast<__half2*>(&g_aexp[r1]) = h1;
        *reinterpret_cast<__half2*>(&g_aexp[r1 + 512]) = l1h;
    }
}

// ---------------- launch ----------------
extern "C" void kernel_launch(void* const* d_in, const int* in_sizes, int n_in,
                              void* d_out, int out_size) {
    const float* x      = (const float*)d_in[0];
    const float* w_qkv  = (const float*)d_in[1];
    const float* w_o    = (const float*)d_in[2];
    const float* lscale = (const float*)d_in[3];
    const float* lls    = (const float*)d_in[4];
    float* out = (float*)d_out;

    __half *aexp, *bexp, *bexp2;
    cudaGetSymbolAddress((void**)&aexp, g_aexp);
    cudaGetSymbolAddress((void**)&bexp, g_bexp);
    cudaGetSymbolAddress((void**)&bexp2, g_bexp2);

    const int M = BATCH * NSEQ;   // 4096
    cudaFuncSetAttribute(attn3_kernel, cudaFuncAttributeMaxDynamicSharedMemorySize, ATT_SMEM);
    cudaFuncSetAttribute(mmagemm<0>, cudaFuncAttributeMaxDynamicSharedMemorySize, GEMM_SMEM);
    cudaFuncSetAttribute(mmagemm<1>, cudaFuncAttributeMaxDynamicSharedMemorySize, GEMM_SMEM);

    // 1) theta/cos/sin + per-key bias (needed by GEMM1 epilogue + attention)
    prep_kernel<<<(NHEADS * NSEQ + 127) / 128, 128>>>(lscale, lls);

    // 2) fp16x2 conversions for QKV GEMM + out-proj weights
    convA_kernel<<<(M * 128 + 255) / 256, 256>>>(x, aexp, M);
    convB_kernel<<<(3 * DMODEL * DMODEL + 255) / 256, 256>>>(w_qkv, bexp, 3 * DMODEL);
    convB_kernel<<<(DMODEL * DMODEL + 255) / 256, 256>>>(w_o, bexp2, DMODEL);

    // 3) QKV projection; epilogue rotates and emits fp16 Q/K/V
    mmagemm<0><<<dim3(3 * DMODEL / 128, M / 128), 256, GEMM_SMEM>>>(aexp, bexp, nullptr, 3 * DMODEL);

    // 4) fp16 tensor-core flash attention; epilogue writes split A' for out-proj
    attn3_kernel<<<dim3(BATCH * NHEADS, NSEQ / 128), 256, ATT_SMEM>>>();

    // 5) output projection
    mmagemm<1><<<dim3(DMODEL / 128, M / 128), 256, GEMM_SMEM>>>(aexp, bexp2, out, DMODEL);
}

// round 13
// speedup vs baseline: 2.0417x; 1.0817x over previous
#include <cuda_runtime.h>
#include <cuda_bf16.h>
#include <cuda_fp16.h>
#include <cstdint>
#include <math.h>

#define BATCH   2
#define NSEQ    2048
#define DMODEL  512
#define NHEADS  8
#define DH      64
#define KP      32
#define KEXP    1024
#define TAU_F   6.283185307179586f

// ---------------- scratch (static device memory; no allocations) ----------------
__device__ __half g_qe[(size_t)BATCH * NHEADS * NSEQ * DH];          // fp16 rotated Q
__device__ __half g_ke[(size_t)BATCH * NHEADS * NSEQ * DH];          // fp16 rotated K
__device__ __half g_vh[(size_t)BATCH * NHEADS * NSEQ * DH];          // fp16 V
__device__ float g_cos[NHEADS * NSEQ * KP];
__device__ float g_sin[NHEADS * NSEQ * KP];
__device__ float g_bias[NHEADS * NSEQ];                              // lam*S_n/KP per head
__device__ __half g_aexp[(size_t)BATCH * NSEQ * KEXP];               // A' = [Ah|Al]
__device__ __half g_bexp[(size_t)3 * DMODEL * KEXP];                 // B' = [Bh|Bh] (w_qkv)
__device__ __half g_bexp2[(size_t)DMODEL * KEXP];                    // B2' = [Bh|Bh] (w_o)

__constant__ float c_zim[KP] = {
    14.134725142f, 21.022039639f, 25.01085758f,  30.424876126f,
    32.935061588f, 37.586178159f, 40.918719012f, 43.327073281f,
    48.005150881f, 49.773832478f, 52.970321478f, 56.446247697f,
    59.347044003f, 60.831778525f, 65.112544048f, 67.079810529f,
    69.546401711f, 72.067157674f, 75.704690699f, 77.144840069f,
    79.33737502f,  82.910380854f, 84.735492981f, 87.425274613f,
    88.809111208f, 92.491899271f, 94.651344041f, 95.870634228f,
    98.831194218f, 101.317851006f, 103.72553804f, 105.446623052f};

// ---------------- warp-MMA / async helpers (portable sm_80+ path) ----------------
__device__ __forceinline__ uint32_t smem_u32(const void* p) {
    uint32_t a;
    asm("{ .reg .u64 t; cvta.to.shared.u64 t, %1; cvt.u32.u64 %0, t; }" : "=r"(a) : "l"(p));
    return a;
}
__device__ __forceinline__ void ldsm4(uint32_t* r, uint32_t a) {
    asm volatile("ldmatrix.sync.aligned.m8n8.x4.shared.b16 {%0,%1,%2,%3}, [%4];"
                 : "=r"(r[0]), "=r"(r[1]), "=r"(r[2]), "=r"(r[3]) : "r"(a));
}
__device__ __forceinline__ void ldsm4t(uint32_t* r, uint32_t a) {
    asm volatile("ldmatrix.sync.aligned.m8n8.x4.trans.shared.b16 {%0,%1,%2,%3}, [%4];"
                 : "=r"(r[0]), "=r"(r[1]), "=r"(r[2]), "=r"(r[3]) : "r"(a));
}
__device__ __forceinline__ void mma16816h(float* c, const uint32_t* a, uint32_t b0, uint32_t b1) {
    asm volatile("mma.sync.aligned.m16n8k16.row.col.f32.f16.f16.f32 "
                 "{%0,%1,%2,%3}, {%4,%5,%6,%7}, {%8,%9}, {%0,%1,%2,%3};"
                 : "+f"(c[0]), "+f"(c[1]), "+f"(c[2]), "+f"(c[3])
                 : "r"(a[0]), "r"(a[1]), "r"(a[2]), "r"(a[3]), "r"(b0), "r"(b1));
}
__device__ __forceinline__ void cpasync16(uint32_t dst, const void* src) {
    asm volatile("cp.async.cg.shared.global [%0], [%1], 16;" :: "r"(dst), "l"(src));
}
__device__ __forceinline__ void cpcommit() {
    asm volatile("cp.async.commit_group;");
}
template <int N>
__device__ __forceinline__ void cpwait() {
    asm volatile("cp.async.wait_group %0;" :: "n"(N));
}

// ---------------- fp16x2 mma GEMM: 8 warps x (64x32), fragment-pipelined ----------
// C[M,Ntot] = A'[M,1024] @ B'[Ntot,1024]^T  ( = A @ Bh exactly, fp16x2 split)
#define KT (KEXP / 32)
#define SWZ(r, bc) ((uint32_t)((r) * 64 + ((bc) ^ ((((r) >> 1) & 3) << 4))))
#define GSTAGES 4
#define GSTG_SZ 16384               // A(8KB) + B(8KB) per stage
#define GEMM_SMEM (GSTAGES * GSTG_SZ)

template <int EPI>
__global__ __launch_bounds__(256, 2) void mmagemm(const __half* __restrict__ A,
                                                  const __half* __restrict__ Bm,
                                                  float* __restrict__ C, int Ntot) {
    extern __shared__ char gsm[];
    const uint32_t sbase = smem_u32(gsm);

    const int tid = threadIdx.x;
    const int lane = tid & 31;
    const int wid = tid >> 5;
    const int wm = (wid & 1) * 64;
    const int wn = (wid >> 1) * 32;
    const int row0 = blockIdx.y * 128;
    const int col0 = blockIdx.x * 128;

    const int lr = (lane & 7) + ((lane >> 3) & 1) * 8;
    const int kh = (lane >> 4) * 16;
    uint32_t aoff[4][2], boff[2][2];
#pragma unroll
    for (int mi = 0; mi < 4; mi++)
#pragma unroll
        for (int ks = 0; ks < 2; ks++) aoff[mi][ks] = SWZ(wm + mi * 16 + lr, ks * 32 + kh);
#pragma unroll
    for (int g = 0; g < 2; g++)
#pragma unroll
        for (int ks = 0; ks < 2; ks++) boff[g][ks] = SWZ(wn + g * 16 + lr, ks * 32 + kh);

    const int r_ld0 = tid >> 2, cu_ld = tid & 3;
    const int r_ld1 = r_ld0 + 64;
    const uint32_t so0 = SWZ(r_ld0, cu_ld * 16);
    const uint32_t so1 = SWZ(r_ld1, cu_ld * 16);
    const __half* a0p = &A[(size_t)(row0 + r_ld0) * KEXP + cu_ld * 8];
    const __half* a1p = &A[(size_t)(row0 + r_ld1) * KEXP + cu_ld * 8];
    const __half* b0p = &Bm[(size_t)(col0 + r_ld0) * KEXP + cu_ld * 8];
    const __half* b1p = &Bm[(size_t)(col0 + r_ld1) * KEXP + cu_ld * 8];

    auto load_tile = [&](int t) {
        const uint32_t st = sbase + (uint32_t)((t & (GSTAGES - 1)) * GSTG_SZ);
        const int k0 = t * 32;
        cpasync16(st + so0, a0p + k0);
        cpasync16(st + so1, a1p + k0);
        cpasync16(st + 8192 + so0, b0p + k0);
        cpasync16(st + 8192 + so1, b1p + k0);
        cpcommit();
    };
    load_tile(0);
    load_tile(1);
    load_tile(2);

    float acc[4][4][4];
#pragma unroll
    for (int mi = 0; mi < 4; mi++)
#pragma unroll
        for (int ni = 0; ni < 4; ni++)
#pragma unroll
            for (int q = 0; q < 4; q++) acc[mi][ni][q] = 0.0f;

    uint32_t af[2][4][4], bfr[2][2][4];

    cpwait<1>();
    __syncthreads();
    {
        const uint32_t bA = sbase;
#pragma unroll
        for (int mi = 0; mi < 4; mi++) ldsm4(af[0][mi], bA + aoff[mi][0]);
#pragma unroll
        for (int g = 0; g < 2; g++) ldsm4(bfr[0][g], bA + 8192 + boff[g][0]);
    }

    for (int t = 0; t < KT; t++) {
        const uint32_t bA = sbase + (uint32_t)((t & (GSTAGES - 1)) * GSTG_SZ);
        const int tn = (t + 1 < KT) ? t + 1 : t;
        const uint32_t bA1 = sbase + (uint32_t)((tn & (GSTAGES - 1)) * GSTG_SZ);

#pragma unroll
        for (int mi = 0; mi < 4; mi++) ldsm4(af[1][mi], bA + aoff[mi][1]);
#pragma unroll
        for (int g = 0; g < 2; g++) ldsm4(bfr[1][g], bA + 8192 + boff[g][1]);
#pragma unroll
        for (int mi = 0; mi < 4; mi++)
#pragma unroll
            for (int ni = 0; ni < 4; ni++)
                mma16816h(acc[mi][ni], af[0][mi], bfr[0][ni >> 1][ni & 1], bfr[0][ni >> 1][(ni & 1) + 2]);

#pragma unroll
        for (int mi = 0; mi < 4; mi++) ldsm4(af[0][mi], bA1 + aoff[mi][0]);
#pragma unroll
        for (int g = 0; g < 2; g++) ldsm4(bfr[0][g], bA1 + 8192 + boff[g][0]);
#pragma unroll
        for (int mi = 0; mi < 4; mi++)
#pragma unroll
            for (int ni = 0; ni < 4; ni++)
                mma16816h(acc[mi][ni], af[1][mi], bfr[1][ni >> 1][ni & 1], bfr[1][ni >> 1][(ni & 1) + 2]);

        if (t + 3 < KT) load_tile(t + 3);
        else cpcommit();
        cpwait<1>();
        __syncthreads();
    }

    // epilogue
#pragma unroll
    for (int mi = 0; mi < 4; mi++) {
#pragma unroll
        for (int ni = 0; ni < 4; ni++) {
            int m0 = row0 + wm + mi * 16 + (lane >> 2);
            int n = col0 + wn + ni * 8 + (lane & 3) * 2;
#pragma unroll
            for (int half = 0; half < 2; half++) {
                int m = m0 + half * 8;
                float v0 = acc[mi][ni][half * 2 + 0];
                float v1 = acc[mi][ni][half * 2 + 1];
                if (EPI == 1) {
                    *reinterpret_cast<float2*>(&C[(size_t)m * Ntot + n]) = make_float2(v0, v1);
                } else {
                    const int bb = m >> 11, nn = m & 2047;
                    const int sect = n >> 9;
                    const int h = (n >> 6) & 7;
                    const int d = n & 63;
                    size_t ob = ((size_t)((bb * NHEADS + h) * NSEQ) + nn) * DH + d;
                    if (sect == 2) {
                        *reinterpret_cast<__half2*>(&g_vh[ob]) =
                            __float22half2_rn(make_float2(v0, v1));
                    } else {
                        int ci = (h * NSEQ + nn) * KP + (d >> 1);
                        float c0 = g_cos[ci], s0 = g_sin[ci];
                        __half2 o2 = __float22half2_rn(
                            make_float2(v0 * c0 - v1 * s0, v0 * s0 + v1 * c0));
                        if (sect == 0) *reinterpret_cast<__half2*>(&g_qe[ob]) = o2;
                        else           *reinterpret_cast<__half2*>(&g_ke[ob]) = o2;
                    }
                }
            }
        }
    }
}

// ---------------- fp16x2 split conversions ----------------
// A' = [Ah | Al] along K (exact representation of A)
__global__ void convA_kernel(const float* __restrict__ src, __half* __restrict__ dst, int M) {
    int i = blockIdx.x * blockDim.x + threadIdx.x;
    if (i >= M * 128) return;
    int row = i >> 7, c4 = (i & 127) * 4;
    float4 v = *reinterpret_cast<const float4*>(&src[(size_t)row * DMODEL + c4]);
    __half h0 = __float2half(v.x), h1 = __float2half(v.y);
    __half h2 = __float2half(v.z), h3 = __float2half(v.w);
    __half l0 = __float2half(v.x - __half2float(h0));
    __half l1 = __float2half(v.y - __half2float(h1));
    __half l2 = __float2half(v.z - __half2float(h2));
    __half l3 = __float2half(v.w - __half2float(h3));
    size_t base = (size_t)row * KEXP + c4;
    __half2* d0 = reinterpret_cast<__half2*>(&dst[base]);
    __half2* d1 = reinterpret_cast<__half2*>(&dst[base + 512]);
    d0[0] = __half2(h0, h1); d0[1] = __half2(h2, h3);
    d1[0] = __half2(l0, l1); d1[1] = __half2(l2, l3);
}

// Fused weight conversion: rows 0..1535 -> g_bexp (w_qkv), rows 1536..2047 -> g_bexp2 (w_o)
__global__ void convW_kernel(const float* __restrict__ w_qkv, const float* __restrict__ w_o) {
    int i = blockIdx.x * blockDim.x + threadIdx.x;
    if (i >= 2048 * DMODEL) return;
    int k = i & 511, n = i >> 9;
    if (n < 3 * DMODEL) {
        __half hi = __float2half(w_qkv[(size_t)k * (3 * DMODEL) + n]);
        size_t base = (size_t)n * KEXP + k;
        g_bexp[base] = hi;
        g_bexp[base + 512] = hi;
    } else {
        int n2 = n - 3 * DMODEL;
        __half hi = __float2half(w_o[(size_t)k * DMODEL + n2]);
        size_t base = (size_t)n2 * KEXP + k;
        g_bexp2[base] = hi;
        g_bexp2[base + 512] = hi;
    }
}

// ---------------- theta / cos / sin / per-key bias ----------------
__global__ void prep_kernel(const float* __restrict__ log_scale,
                            const float* __restrict__ log_lambda_sigma) {
    int idx = blockIdx.x * blockDim.x + threadIdx.x;
    if (idx >= NHEADS * NSEQ) return;
    int h = idx / NSEQ;
    int n = idx % NSEQ;
    float sc = expf(log_scale[h]);
    float lam = expf(log_lambda_sigma[h]);
    float tau = log1pf((float)n);
    float ssum = 0.0f;
#pragma unroll
    for (int p = 0; p < KP; p++) {
        float g = c_zim[p] / c_zim[0];
        float th = tau * g * sc;
        g_cos[idx * KP + p] = cosf(th);
        g_sin[idx * KP + p] = sinf(th);
        ssum += floorf(th / TAU_F);
    }
    g_bias[idx] = lam * ssum * (1.0f / KP);
}

// ---------------- tensor-core flash attention, single fp16 MMA path ----------
// Q/K/V fp16 (64 cols, pitch 144B). Epilogue writes fp16x2 [Oh|Ol] into g_aexp.
// Balanced static schedule: first 148 bids take the largest blocks descending,
// remaining bids ascending, so co-resident CTA pairs (bid, bid+148) sum ~34 units.
#define VPITCH 144
#define QOFF   0
#define QSZ    (128 * VPITCH)                      // 18432
#define KSZ    (64 * VPITCH)                       // 9216
#define STSZ   (2 * KSZ + 256)                     // K + V + bias = 18688
#define KOFF(s)  (QSZ + (s) * STSZ)
#define VHOFF(s) (KOFF(s) + KSZ)
#define BOFF(s)  (VHOFF(s) + KSZ)
#define ATT_SMEM (QSZ + 2 * STSZ)                  // 55808

__global__ __launch_bounds__(256, 2) void attn3_kernel() {
    extern __shared__ char smc[];
    const uint32_t smb = smem_u32(smc);
    const int tid = threadIdx.x;
    const int lane = tid & 31;
    const int wid = tid >> 5;

    // balanced (bh, qblock) schedule from linear bid
    const int bid = blockIdx.x;
    int qb, bh;
    if (bid < 144)      { qb = 15 - (bid >> 4); bh = bid & 15; }        // sizes 32..16
    else if (bid < 148) { qb = 6; bh = bid - 144; }                     // size 14, bh 0..3
    else {
        int j = bid - 148;
        if (j < 96) { qb = j >> 4; bh = j & 15; }                       // sizes 2..12
        else        { qb = 6; bh = j - 96 + 4; }                        // size 14, bh 4..15
    }
    const int h = bh & (NHEADS - 1);
    const int b = bh >> 3;
    const int qbase = qb << 7;
    const int ntiles = (qbase >> 6) + 2;

    const __half* qe = g_qe + (size_t)bh * NSEQ * DH;
    const __half* ke = g_ke + (size_t)bh * NSEQ * DH;
    const __half* vh = g_vh + (size_t)bh * NSEQ * DH;
    const float* bp = g_bias + h * NSEQ;

    for (int i = tid; i < 1024; i += 256) {
        int r = i >> 3, c = i & 7;
        cpasync16(smb + QOFF + r * VPITCH + c * 16, qe + (size_t)(qbase + r) * DH + c * 8);
    }
    auto load_tile = [&](int t, int st) {
        int jg = t << 6;
#pragma unroll
        for (int q = 0; q < 2; q++) {
            int i = q * 256 + tid, r = i >> 3, c = i & 7;
            cpasync16(smb + KOFF(st) + r * VPITCH + c * 16, ke + (size_t)(jg + r) * DH + c * 8);
            cpasync16(smb + VHOFF(st) + r * VPITCH + c * 16, vh + (size_t)(jg + r) * DH + c * 8);
        }
        if (tid < 16) cpasync16(smb + BOFF(st) + tid * 16, bp + jg + tid * 4);
    };
    load_tile(0, 0);
    cpcommit();
    load_tile(1, 1);
    cpcommit();

    const uint32_t qaddr = smb + QOFF + (wid * 16 + (lane & 15)) * VPITCH + (lane >> 4) * 16;
    const uint32_t klocal = (uint32_t)((lane & 15) * VPITCH + (lane >> 4) * 16);

    float o[8][4];
#pragma unroll
    for (int i = 0; i < 8; i++)
#pragma unroll
        for (int q = 0; q < 4; q++) o[i][q] = 0.0f;
    float m0 = -INFINITY, m1 = -INFINITY, l0 = 0.0f, l1 = 0.0f;
    const int qm0 = qbase + wid * 16 + (lane >> 2);
    const int qm1 = qm0 + 8;

    for (int t = 0; t < ntiles; t++) {
        if (t < ntiles - 1) cpwait<1>(); else cpwait<0>();
        __syncthreads();
        const int st = t & 1;
        const int jg = t << 6;

        float s[8][4];
#pragma unroll
        for (int i = 0; i < 8; i++)
#pragma unroll
            for (int q = 0; q < 4; q++) s[i][q] = 0.0f;
        const uint32_t kb = smb + KOFF(st);
#pragma unroll
        for (int ks = 0; ks < 4; ks++) {
            uint32_t a[4];
            ldsm4(a, qaddr + ks * 32);
#pragma unroll
            for (int ng = 0; ng < 4; ng++) {
                uint32_t bfr[4];
                ldsm4(bfr, kb + klocal + ng * (16 * VPITCH) + ks * 32);
                mma16816h(s[2 * ng],     a, bfr[0], bfr[2]);
                mma16816h(s[2 * ng + 1], a, bfr[1], bfr[3]);
            }
        }

        const bool masked = (t >= ntiles - 2);
#pragma unroll
        for (int nf = 0; nf < 8; nf++) {
            int col = jg + nf * 8 + ((lane & 3) << 1);
            float2 bj = *reinterpret_cast<const float2*>(smc + BOFF(st) + (nf * 8 + ((lane & 3) << 1)) * 4);
            s[nf][0] = s[nf][0] * 0.125f + bj.x;
            s[nf][1] = s[nf][1] * 0.125f + bj.y;
            s[nf][2] = s[nf][2] * 0.125f + bj.x;
            s[nf][3] = s[nf][3] * 0.125f + bj.y;
            if (masked) {
                if (col > qm0)     s[nf][0] = -INFINITY;
                if (col + 1 > qm0) s[nf][1] = -INFINITY;
                if (col > qm1)     s[nf][2] = -INFINITY;
                if (col + 1 > qm1) s[nf][3] = -INFINITY;
            }
        }

        float mx0 = -INFINITY, mx1 = -INFINITY;
#pragma unroll
        for (int nf = 0; nf < 8; nf++) {
            mx0 = fmaxf(mx0, fmaxf(s[nf][0], s[nf][1]));
            mx1 = fmaxf(mx1, fmaxf(s[nf][2], s[nf][3]));
        }
        mx0 = fmaxf(mx0, __shfl_xor_sync(0xffffffffu, mx0, 1));
        mx0 = fmaxf(mx0, __shfl_xor_sync(0xffffffffu, mx0, 2));
        mx1 = fmaxf(mx1, __shfl_xor_sync(0xffffffffu, mx1, 1));
        mx1 = fmaxf(mx1, __shfl_xor_sync(0xffffffffu, mx1, 2));
        float mn0 = fmaxf(m0, mx0), mn1 = fmaxf(m1, mx1);
        float corr0 = __expf(m0 - mn0), corr1 = __expf(m1 - mn1);
        m0 = mn0; m1 = mn1;
        float ps0 = 0.0f, ps1 = 0.0f;
#pragma unroll
        for (int nf = 0; nf < 8; nf++) {
            s[nf][0] = __expf(s[nf][0] - mn0);
            s[nf][1] = __expf(s[nf][1] - mn0);
            s[nf][2] = __expf(s[nf][2] - mn1);
            s[nf][3] = __expf(s[nf][3] - mn1);
            ps0 += s[nf][0] + s[nf][1];
            ps1 += s[nf][2] + s[nf][3];
        }
        ps0 += __shfl_xor_sync(0xffffffffu, ps0, 1);
        ps0 += __shfl_xor_sync(0xffffffffu, ps0, 2);
        ps1 += __shfl_xor_sync(0xffffffffu, ps1, 1);
        ps1 += __shfl_xor_sync(0xffffffffu, ps1, 2);
        l0 = l0 * corr0 + ps0;
        l1 = l1 * corr1 + ps1;
#pragma unroll
        for (int nf = 0; nf < 8; nf++) {
            o[nf][0] *= corr0; o[nf][1] *= corr0;
            o[nf][2] *= corr1; o[nf][3] *= corr1;
        }

        const uint32_t vhb = smb + VHOFF(st);
#pragma unroll
        for (int ks2 = 0; ks2 < 4; ks2++) {
            const int f0 = 2 * ks2, f1 = 2 * ks2 + 1;
            __half2 p0 = __float22half2_rn(make_float2(s[f0][0], s[f0][1]));
            __half2 p1 = __float22half2_rn(make_float2(s[f0][2], s[f0][3]));
            __half2 p2 = __float22half2_rn(make_float2(s[f1][0], s[f1][1]));
            __half2 p3 = __float22half2_rn(make_float2(s[f1][2], s[f1][3]));
            uint32_t ah[4] = {*(uint32_t*)&p0, *(uint32_t*)&p1, *(uint32_t*)&p2, *(uint32_t*)&p3};
#pragma unroll
            for (int dseg = 0; dseg < 4; dseg++) {
                uint32_t bhf[4];
                ldsm4t(bhf, vhb + ks2 * (16 * VPITCH) + klocal + dseg * 32);
                mma16816h(o[2 * dseg],     ah, bhf[0], bhf[1]);
                mma16816h(o[2 * dseg + 1], ah, bhf[2], bhf[3]);
            }
        }

        __syncthreads();
        if (t + 2 < ntiles) { load_tile(t + 2, st); cpcommit(); }
    }

    // ---- normalize + write fp16x2 split [Oh|Ol] directly into g_aexp ----
    const float inv0 = 1.0f / l0, inv1 = 1.0f / l1;
#pragma unroll
    for (int nf = 0; nf < 8; nf++) {
        int col = h * DH + nf * 8 + ((lane & 3) << 1);
        size_t r0 = (size_t)(b * NSEQ + qm0) * KEXP + col;
        size_t r1 = (size_t)(b * NSEQ + qm1) * KEXP + col;
        float x0 = o[nf][0] * inv0, y0 = o[nf][1] * inv0;
        float x1 = o[nf][2] * inv1, y1 = o[nf][3] * inv1;
        __half2 h0 = __float22half2_rn(make_float2(x0, y0));
        __half2 l0h = __float22half2_rn(
            make_float2(x0 - __low2float(h0), y0 - __high2float(h0)));
        __half2 h1 = __float22half2_rn(make_float2(x1, y1));
        __half2 l1h = __float22half2_rn(
            make_float2(x1 - __low2float(h1), y1 - __high2float(h1)));
        *reinterpret_cast<__half2*>(&g_aexp[r0]) = h0;
        *reinterpret_cast<__half2*>(&g_aexp[r0 + 512]) = l0h;
        *reinterpret_cast<__half2*>(&g_aexp[r1]) = h1;
        *reinterpret_cast<__half2*>(&g_aexp[r1 + 512]) = l1h;
    }
}

// ---------------- launch ----------------
extern "C" void kernel_launch(void* const* d_in, const int* in_sizes, int n_in,
                              void* d_out, int out_size) {
    const float* x      = (const float*)d_in[0];
    const float* w_qkv  = (const float*)d_in[1];
    const float* w_o    = (const float*)d_in[2];
    const float* lscale = (const float*)d_in[3];
    const float* lls    = (const float*)d_in[4];
    float* out = (float*)d_out;

    __half *aexp, *bexp, *bexp2;
    cudaGetSymbolAddress((void**)&aexp, g_aexp);
    cudaGetSymbolAddress((void**)&bexp, g_bexp);
    cudaGetSymbolAddress((void**)&bexp2, g_bexp2);

    const int M = BATCH * NSEQ;   // 4096
    cudaFuncSetAttribute(attn3_kernel, cudaFuncAttributeMaxDynamicSharedMemorySize, ATT_SMEM);
    cudaFuncSetAttribute(mmagemm<0>, cudaFuncAttributeMaxDynamicSharedMemorySize, GEMM_SMEM);
    cudaFuncSetAttribute(mmagemm<1>, cudaFuncAttributeMaxDynamicSharedMemorySize, GEMM_SMEM);

    // 1) theta/cos/sin + per-key bias (needed by GEMM1 epilogue + attention)
    prep_kernel<<<(NHEADS * NSEQ + 127) / 128, 128>>>(lscale, lls);

    // 2) fp16x2 conversions: activations + both weight matrices (fused)
    convA_kernel<<<(M * 128 + 255) / 256, 256>>>(x, aexp, M);
    convW_kernel<<<(2048 * DMODEL + 255) / 256, 256>>>(w_qkv, w_o);

    // 3) QKV projection; epilogue rotates and emits fp16 Q/K/V
    mmagemm<0><<<dim3(3 * DMODEL / 128, M / 128), 256, GEMM_SMEM>>>(aexp, bexp, nullptr, 3 * DMODEL);

    // 4) fp16 tensor-core flash attention (balanced schedule); writes split A'
    attn3_kernel<<<256, 256, ATT_SMEM>>>();

    // 5) output projection
    mmagemm<1><<<dim3(DMODEL / 128, M / 128), 256, GEMM_SMEM>>>(aexp, bexp2, out, DMODEL);
}